// round 12
// baseline (speedup 1.0000x reference)
#include <cuda_runtime.h>
#include <math.h>
#include <stdint.h>

#define Bn 256
#define Mn 512
#define Dn 512
#define Cn 8
#define U1 512
#define U2 256
#define U3 128

// Scratch (device-code-only references)
__device__ float g_pooled[Bn * Dn];          // (B, D)
__device__ float g_h1[Cn * Bn * U1];         // (C, B, 512)
__device__ float g_h2[Cn * Bn * U2];         // (C, B, 256)
__device__ float g_term[Cn * Bn];            // per (c,b) loss term

// ---------------------------------------------------------------------------
// bf16 helpers
// ---------------------------------------------------------------------------
__device__ __forceinline__ uint32_t packbf(float lo, float hi) {
    uint32_t r;
    asm("cvt.rn.bf16x2.f32 %0, %1, %2;" : "=r"(r) : "f"(hi), "f"(lo));
    return r;
}
__device__ __forceinline__ void split2(float x0, float x1,
                                       uint32_t& h, uint32_t& l) {
    h = packbf(x0, x1);
    const float h0 = __uint_as_float(h << 16);
    const float h1 = __uint_as_float(h & 0xffff0000u);
    l = packbf(x0 - h0, x1 - h1);
}
__device__ __forceinline__ void mma16(float* d, const uint32_t* a, const uint32_t* b) {
    asm("mma.sync.aligned.m16n8k16.row.col.f32.bf16.bf16.f32 "
        "{%0,%1,%2,%3}, {%4,%5,%6,%7}, {%8,%9}, {%0,%1,%2,%3};"
        : "+f"(d[0]), "+f"(d[1]), "+f"(d[2]), "+f"(d[3])
        : "r"(a[0]), "r"(a[1]), "r"(a[2]), "r"(a[3]), "r"(b[0]), "r"(b[1]));
}

// ---------------------------------------------------------------------------
// 1) Masked sum pooling (proven version)
// ---------------------------------------------------------------------------
__global__ __launch_bounds__(256) void pool_kernel(const float* __restrict__ ec,
                                                   const float* __restrict__ mask) {
    const int b = blockIdx.x;
    const int dbase = blockIdx.y * 256;
    const int tid = threadIdx.x;

    __shared__ float keep[Mn];
    for (int i = tid; i < Mn; i += 256)
        keep[i] = (mask[b * Mn + i] == 0.0f) ? 1.0f : 0.0f;
    __syncthreads();

    const float* p = ec + ((size_t)b * Mn) * Dn + dbase + tid;
    float a0 = 0.f, a1 = 0.f, a2 = 0.f, a3 = 0.f;
#pragma unroll 4
    for (int m = 0; m < Mn; m += 4) {
        a0 = fmaf(p[(size_t)(m + 0) * Dn], keep[m + 0], a0);
        a1 = fmaf(p[(size_t)(m + 1) * Dn], keep[m + 1], a1);
        a2 = fmaf(p[(size_t)(m + 2) * Dn], keep[m + 2], a2);
        a3 = fmaf(p[(size_t)(m + 3) * Dn], keep[m + 3], a3);
    }
    g_pooled[b * Dn + dbase + tid] = (a0 + a1) + (a2 + a3);
}

// ---------------------------------------------------------------------------
// 2) Layers 1+2: bf16x3 tensor-core GEMM (proven round-11 version).
// ---------------------------------------------------------------------------
template <int LAYER>
__global__ __launch_bounds__(256) void gemm_bf16_kernel(
        const float* __restrict__ W, const float* __restrict__ bias) {
    constexpr int K = (LAYER == 1) ? Dn : U1;
    constexpr int N = (LAYER == 1) ? U1 : U2;
    constexpr bool AHASC = (LAYER != 1);
    const float* Aroot = (LAYER == 1) ? g_pooled : g_h1;
    float* Oroot       = (LAYER == 1) ? g_h1     : g_h2;

    const int c  = blockIdx.z;
    const int b0 = blockIdx.y * 64;
    const int n0 = blockIdx.x * 64;
    const int tid = threadIdx.x;
    const int lane = tid & 31;
    const int warp = tid >> 5;
    const int wm = warp >> 2;       // 0..1
    const int wn = warp & 3;        // 0..3
    const int g  = lane >> 2;       // 0..7
    const int tg = lane & 3;        // 0..3

    __shared__ uint32_t Ah[64][20], Al[64][20];   // [m][k2] packed bf16x2
    __shared__ uint32_t Wh[16][72], Wl[16][72];   // [k2][n] packed bf16x2

    float acc[2][2][4] = {};

    const float* Ag = Aroot + (AHASC ? (size_t)c * Bn * K : 0) + (size_t)b0 * K;
    const float* Wg = W + (size_t)c * K * N + n0;

    const int arow  = tid >> 2;          // 0..63
    const int acol2 = (tid & 3) * 4;     // packed col 0,4,8,12
    const int acolf = (tid & 3) * 8;     // float col
    const int wr2   = tid >> 4;          // 0..15 packed k row
    const int wc4   = (tid & 15) * 4;    // n col 0..60

    float4 gwa = *(const float4*)(Wg + (size_t)(2 * wr2) * N + wc4);
    float4 gwb = *(const float4*)(Wg + (size_t)(2 * wr2 + 1) * N + wc4);

    cudaGridDependencySynchronize();

    for (int k0 = 0; k0 < K; k0 += 32) {
        float4 ga0 = *(const float4*)(Ag + (size_t)arow * K + k0 + acolf);
        float4 ga1 = *(const float4*)(Ag + (size_t)arow * K + k0 + acolf + 4);

        __syncthreads();
        {
            uint32_t hp[4], lp[4];
            split2(ga0.x, ga0.y, hp[0], lp[0]);
            split2(ga0.z, ga0.w, hp[1], lp[1]);
            split2(ga1.x, ga1.y, hp[2], lp[2]);
            split2(ga1.z, ga1.w, hp[3], lp[3]);
            *(uint4*)&Ah[arow][acol2] = make_uint4(hp[0], hp[1], hp[2], hp[3]);
            *(uint4*)&Al[arow][acol2] = make_uint4(lp[0], lp[1], lp[2], lp[3]);
        }
        {
            uint32_t hw[4], lw[4];
            split2(gwa.x, gwb.x, hw[0], lw[0]);
            split2(gwa.y, gwb.y, hw[1], lw[1]);
            split2(gwa.z, gwb.z, hw[2], lw[2]);
            split2(gwa.w, gwb.w, hw[3], lw[3]);
            *(uint4*)&Wh[wr2][wc4] = make_uint4(hw[0], hw[1], hw[2], hw[3]);
            *(uint4*)&Wl[wr2][wc4] = make_uint4(lw[0], lw[1], lw[2], lw[3]);
        }
        __syncthreads();

        if (k0 + 32 < K) {
            gwa = *(const float4*)(Wg + (size_t)(k0 + 32 + 2 * wr2) * N + wc4);
            gwb = *(const float4*)(Wg + (size_t)(k0 + 32 + 2 * wr2 + 1) * N + wc4);
        }

#pragma unroll
        for (int kk = 0; kk < 2; kk++) {
            const int kb2 = kk * 8;
            uint32_t ah[2][4], al_[2][4], bh[2][2], bl[2][2];
#pragma unroll
            for (int mi = 0; mi < 2; mi++) {
                const int m = wm * 32 + mi * 16 + g;
                ah[mi][0]  = Ah[m][kb2 + tg];     ah[mi][1]  = Ah[m + 8][kb2 + tg];
                ah[mi][2]  = Ah[m][kb2 + tg + 4]; ah[mi][3]  = Ah[m + 8][kb2 + tg + 4];
                al_[mi][0] = Al[m][kb2 + tg];     al_[mi][1] = Al[m + 8][kb2 + tg];
                al_[mi][2] = Al[m][kb2 + tg + 4]; al_[mi][3] = Al[m + 8][kb2 + tg + 4];
            }
#pragma unroll
            for (int ni = 0; ni < 2; ni++) {
                const int n = wn * 16 + ni * 8 + g;
                bh[ni][0] = Wh[kb2 + tg][n]; bh[ni][1] = Wh[kb2 + tg + 4][n];
                bl[ni][0] = Wl[kb2 + tg][n]; bl[ni][1] = Wl[kb2 + tg + 4][n];
            }
#pragma unroll
            for (int mi = 0; mi < 2; mi++)
#pragma unroll
                for (int ni = 0; ni < 2; ni++) {
                    mma16(acc[mi][ni], ah[mi],  bh[ni]);
                    mma16(acc[mi][ni], ah[mi],  bl[ni]);
                    mma16(acc[mi][ni], al_[mi], bh[ni]);
                }
        }
    }

#pragma unroll
    for (int mi = 0; mi < 2; mi++) {
#pragma unroll
        for (int ni = 0; ni < 2; ni++) {
            const int ncol = n0 + wn * 16 + ni * 8 + tg * 2;
            const float bx = bias[c * N + ncol];
            const float by = bias[c * N + ncol + 1];
            const int r0 = b0 + wm * 32 + mi * 16 + g;
            float2 o0 = {fmaxf(acc[mi][ni][0] + bx, 0.f),
                         fmaxf(acc[mi][ni][1] + by, 0.f)};
            float2 o1 = {fmaxf(acc[mi][ni][2] + bx, 0.f),
                         fmaxf(acc[mi][ni][3] + by, 0.f)};
            *(float2*)(Oroot + ((size_t)(c * Bn + r0)) * N + ncol)     = o0;
            *(float2*)(Oroot + ((size_t)(c * Bn + r0 + 8)) * N + ncol) = o1;
        }
    }
}

// ---------------------------------------------------------------------------
// 3) Layer 3 + L2 normalize on bf16x3 MMA. Tile 64(b) x 128(n full row),
//    K=256, 256 threads (8 warps 2m x 4n, warp tile 32x32).
//    Row ssq: intra-thread -> tg-quartet shuffle -> smem across 4 n-warps.
// ---------------------------------------------------------------------------
__global__ __launch_bounds__(256) void gemm3_norm_kernel(
        const float* __restrict__ W, const float* __restrict__ bias,
        float* __restrict__ zout) {
    constexpr int K = U2;   // 256
    constexpr int N = U3;   // 128
    const int b0 = blockIdx.x * 64;
    const int c  = blockIdx.y;
    const int tid = threadIdx.x;
    const int lane = tid & 31;
    const int warp = tid >> 5;
    const int wm = warp >> 2;       // 0..1
    const int wn = warp & 3;        // 0..3
    const int g  = lane >> 2;       // 0..7
    const int tg = lane & 3;        // 0..3

    __shared__ uint32_t Ah[64][20], Al[64][20];     // [m][k2]
    __shared__ uint32_t Wh[16][136], Wl[16][136];   // [k2][n], stride%32==8
    __shared__ float rowsq[64][4];                  // per-row ssq by n-warp

    float acc[2][4][4] = {};

    const float* Ag = g_h2 + ((size_t)c * Bn + b0) * K;
    const float* Wg = W + (size_t)c * K * N;

    const int arow  = tid >> 2;          // 0..63
    const int acol2 = (tid & 3) * 4;
    const int acolf = (tid & 3) * 8;
    const int wr2   = tid >> 4;          // 0..15
    const int wc4   = (tid & 15) * 4;    // 0..60 (+64 second chunk)

    // W k0=0 tile prefetch before the PDL gate (external input)
    float4 gwa0 = *(const float4*)(Wg + (size_t)(2 * wr2) * N + wc4);
    float4 gwb0 = *(const float4*)(Wg + (size_t)(2 * wr2 + 1) * N + wc4);
    float4 gwa1 = *(const float4*)(Wg + (size_t)(2 * wr2) * N + wc4 + 64);
    float4 gwb1 = *(const float4*)(Wg + (size_t)(2 * wr2 + 1) * N + wc4 + 64);

    cudaGridDependencySynchronize();    // gemm2 must be done before reading h2

    for (int k0 = 0; k0 < K; k0 += 32) {
        float4 ga0 = *(const float4*)(Ag + (size_t)arow * K + k0 + acolf);
        float4 ga1 = *(const float4*)(Ag + (size_t)arow * K + k0 + acolf + 4);

        __syncthreads();
        {
            uint32_t hp[4], lp[4];
            split2(ga0.x, ga0.y, hp[0], lp[0]);
            split2(ga0.z, ga0.w, hp[1], lp[1]);
            split2(ga1.x, ga1.y, hp[2], lp[2]);
            split2(ga1.z, ga1.w, hp[3], lp[3]);
            *(uint4*)&Ah[arow][acol2] = make_uint4(hp[0], hp[1], hp[2], hp[3]);
            *(uint4*)&Al[arow][acol2] = make_uint4(lp[0], lp[1], lp[2], lp[3]);
        }
        {
            uint32_t hw[4], lw[4];
            split2(gwa0.x, gwb0.x, hw[0], lw[0]);
            split2(gwa0.y, gwb0.y, hw[1], lw[1]);
            split2(gwa0.z, gwb0.z, hw[2], lw[2]);
            split2(gwa0.w, gwb0.w, hw[3], lw[3]);
            *(uint4*)&Wh[wr2][wc4] = make_uint4(hw[0], hw[1], hw[2], hw[3]);
            *(uint4*)&Wl[wr2][wc4] = make_uint4(lw[0], lw[1], lw[2], lw[3]);
            split2(gwa1.x, gwb1.x, hw[0], lw[0]);
            split2(gwa1.y, gwb1.y, hw[1], lw[1]);
            split2(gwa1.z, gwb1.z, hw[2], lw[2]);
            split2(gwa1.w, gwb1.w, hw[3], lw[3]);
            *(uint4*)&Wh[wr2][wc4 + 64] = make_uint4(hw[0], hw[1], hw[2], hw[3]);
            *(uint4*)&Wl[wr2][wc4 + 64] = make_uint4(lw[0], lw[1], lw[2], lw[3]);
        }
        __syncthreads();

        if (k0 + 32 < K) {
            gwa0 = *(const float4*)(Wg + (size_t)(k0 + 32 + 2 * wr2) * N + wc4);
            gwb0 = *(const float4*)(Wg + (size_t)(k0 + 32 + 2 * wr2 + 1) * N + wc4);
            gwa1 = *(const float4*)(Wg + (size_t)(k0 + 32 + 2 * wr2) * N + wc4 + 64);
            gwb1 = *(const float4*)(Wg + (size_t)(k0 + 32 + 2 * wr2 + 1) * N + wc4 + 64);
        }

#pragma unroll
        for (int kk = 0; kk < 2; kk++) {
            const int kb2 = kk * 8;
            uint32_t ah[2][4], al_[2][4], bh[4][2], bl[4][2];
#pragma unroll
            for (int mi = 0; mi < 2; mi++) {
                const int m = wm * 32 + mi * 16 + g;
                ah[mi][0]  = Ah[m][kb2 + tg];     ah[mi][1]  = Ah[m + 8][kb2 + tg];
                ah[mi][2]  = Ah[m][kb2 + tg + 4]; ah[mi][3]  = Ah[m + 8][kb2 + tg + 4];
                al_[mi][0] = Al[m][kb2 + tg];     al_[mi][1] = Al[m + 8][kb2 + tg];
                al_[mi][2] = Al[m][kb2 + tg + 4]; al_[mi][3] = Al[m + 8][kb2 + tg + 4];
            }
#pragma unroll
            for (int ni = 0; ni < 4; ni++) {
                const int n = wn * 32 + ni * 8 + g;
                bh[ni][0] = Wh[kb2 + tg][n]; bh[ni][1] = Wh[kb2 + tg + 4][n];
                bl[ni][0] = Wl[kb2 + tg][n]; bl[ni][1] = Wl[kb2 + tg + 4][n];
            }
#pragma unroll
            for (int mi = 0; mi < 2; mi++)
#pragma unroll
                for (int ni = 0; ni < 4; ni++) {
                    mma16(acc[mi][ni], ah[mi],  bh[ni]);
                    mma16(acc[mi][ni], ah[mi],  bl[ni]);
                    mma16(acc[mi][ni], al_[mi], bh[ni]);
                }
        }
    }

    // epilogue: bias + relu (into acc), per-row ssq
    float ss[2][2] = {};
#pragma unroll
    for (int mi = 0; mi < 2; mi++) {
#pragma unroll
        for (int ni = 0; ni < 4; ni++) {
            const int ncol = wn * 32 + ni * 8 + tg * 2;
            const float bx = bias[c * N + ncol];
            const float by = bias[c * N + ncol + 1];
            float h0 = fmaxf(acc[mi][ni][0] + bx, 0.f);
            float h1 = fmaxf(acc[mi][ni][1] + by, 0.f);
            float h2 = fmaxf(acc[mi][ni][2] + bx, 0.f);
            float h3 = fmaxf(acc[mi][ni][3] + by, 0.f);
            acc[mi][ni][0] = h0; acc[mi][ni][1] = h1;
            acc[mi][ni][2] = h2; acc[mi][ni][3] = h3;
            ss[mi][0] = fmaf(h0, h0, ss[mi][0]);
            ss[mi][0] = fmaf(h1, h1, ss[mi][0]);
            ss[mi][1] = fmaf(h2, h2, ss[mi][1]);
            ss[mi][1] = fmaf(h3, h3, ss[mi][1]);
        }
    }
    // reduce over tg quartet (lanes g*4 + tg)
#pragma unroll
    for (int mi = 0; mi < 2; mi++) {
#pragma unroll
        for (int p = 0; p < 2; p++) {
            ss[mi][p] += __shfl_xor_sync(0xffffffffu, ss[mi][p], 1);
            ss[mi][p] += __shfl_xor_sync(0xffffffffu, ss[mi][p], 2);
        }
    }
    if (tg == 0) {
#pragma unroll
        for (int mi = 0; mi < 2; mi++) {
            rowsq[wm * 32 + mi * 16 + g][wn]     = ss[mi][0];
            rowsq[wm * 32 + mi * 16 + g + 8][wn] = ss[mi][1];
        }
    }
    __syncthreads();

#pragma unroll
    for (int mi = 0; mi < 2; mi++) {
        const int lr = wm * 32 + mi * 16 + g;
        const float t0 = ((rowsq[lr][0] + rowsq[lr][1]) + (rowsq[lr][2] + rowsq[lr][3]));
        const float t1 = ((rowsq[lr + 8][0] + rowsq[lr + 8][1]) + (rowsq[lr + 8][2] + rowsq[lr + 8][3]));
        const float r0 = rsqrtf(fmaxf(t0, 1e-12f));
        const float r1 = rsqrtf(fmaxf(t1, 1e-12f));
#pragma unroll
        for (int ni = 0; ni < 4; ni++) {
            const int ncol = wn * 32 + ni * 8 + tg * 2;
            float2 o0 = {acc[mi][ni][0] * r0, acc[mi][ni][1] * r0};
            float2 o1 = {acc[mi][ni][2] * r1, acc[mi][ni][3] * r1};
            *(float2*)(zout + ((size_t)(c * Bn + b0 + lr)) * N + ncol)     = o0;
            *(float2*)(zout + ((size_t)(c * Bn + b0 + lr + 8)) * N + ncol) = o1;
        }
    }
}

// ---------------------------------------------------------------------------
// 4) Per-(c,b) contrastive term. grid (C, 16); 8 warps, 2 rows per warp.
// ---------------------------------------------------------------------------
#define ZPAD 132
__global__ __launch_bounds__(256) void loss_kernel(const float* __restrict__ z,
                                                   const int* __restrict__ label) {
    extern __shared__ float zs[];          // [256][ZPAD]
    __shared__ int slab[Bn];
    __shared__ int wsum[8];

    const int c = blockIdx.x;
    const int tid = threadIdx.x;
    const int lane = tid & 31;
    const int warp = tid >> 5;

    const int myl = label[tid * Cn + c];
    slab[tid] = myl;
    int s = myl;
#pragma unroll
    for (int o = 16; o; o >>= 1) s += __shfl_xor_sync(0xffffffffu, s, o);
    if (lane == 0) wsum[warp] = s;

    cudaGridDependencySynchronize();

    const float* zc = z + (size_t)c * Bn * U3;
    for (int idx = tid; idx < Bn * U3 / 4; idx += 256) {
        const int row = idx >> 5;
        const int c4 = idx & 31;
        float4 v = *(const float4*)(zc + (size_t)row * U3 + c4 * 4);
        *(float4*)&zs[row * ZPAD + c4 * 4] = v;
    }
    __syncthreads();
    int nump = 0;
#pragma unroll
    for (int i = 0; i < 8; i++) nump += wsum[i];

    const int bb = blockIdx.y * 16 + warp * 2;

    int lb[2];
    const float* zb[2];
#pragma unroll
    for (int i = 0; i < 2; i++) {
        lb[i] = slab[bb + i];
        zb[i] = &zs[(bb + i) * ZPAD];
    }

    float es[2] = {0.f, 0.f};
    float ps[2] = {0.f, 0.f};

#pragma unroll
    for (int kk = 0; kk < 8; kk++) {
        const int k = kk * 32 + lane;
        const float* zk = &zs[k * ZPAD];
        float s0 = 0.f, s1 = 0.f;
#pragma unroll
        for (int j = 0; j < U3; j += 4) {
            float4 x  = *(const float4*)(zk + j);
            float4 a0 = *(const float4*)(zb[0] + j);
            float4 a1 = *(const float4*)(zb[1] + j);
            s0 = fmaf(a0.x, x.x, s0); s0 = fmaf(a0.y, x.y, s0);
            s0 = fmaf(a0.z, x.z, s0); s0 = fmaf(a0.w, x.w, s0);
            s1 = fmaf(a1.x, x.x, s1); s1 = fmaf(a1.y, x.y, s1);
            s1 = fmaf(a1.z, x.z, s1); s1 = fmaf(a1.w, x.w, s1);
        }
        const int sk = slab[k];
        float sv[2] = {s0, s1};
#pragma unroll
        for (int i = 0; i < 2; i++) {
            const float ipv = (k == bb + i) ? 0.0f : sv[i] * 2.0f;  // /TEMP
            es[i] += __expf(ipv);
            if (sk == lb[i]) ps[i] += ipv;
        }
    }

#pragma unroll
    for (int i = 0; i < 2; i++) {
#pragma unroll
        for (int o = 16; o; o >>= 1) {
            es[i] += __shfl_xor_sync(0xffffffffu, es[i], o);
            ps[i] += __shfl_xor_sync(0xffffffffu, ps[i], o);
        }
    }
    if (lane == 0) {
#pragma unroll
        for (int i = 0; i < 2; i++) {
            const int numv = lb[i] ? nump : (Bn - nump);
            g_term[c * Bn + bb + i] = ps[i] / (float)numv - logf(es[i]);
        }
    }
}

// ---------------------------------------------------------------------------
// 5) Reduce terms -> losses[c]
// ---------------------------------------------------------------------------
__global__ __launch_bounds__(256) void final_kernel(float* __restrict__ out) {
    __shared__ float red[Bn];
    const int c = blockIdx.x;
    const int tid = threadIdx.x;
    cudaGridDependencySynchronize();
    red[tid] = g_term[c * Bn + tid];
    __syncthreads();
    for (int s = 128; s; s >>= 1) {
        if (tid < s) red[tid] += red[tid + s];
        __syncthreads();
    }
    if (tid == 0) out[(size_t)Cn * Bn * U3 + c] = -red[0];
}

// ---------------------------------------------------------------------------
// Launch with PDL on the capture stream.
// ---------------------------------------------------------------------------
template <typename F, typename... Args>
static void launch_pdl(F f, dim3 grid, dim3 block, size_t smem, Args... args) {
    cudaLaunchConfig_t cfg = {};
    cfg.gridDim = grid;
    cfg.blockDim = block;
    cfg.dynamicSmemBytes = smem;
    cfg.stream = 0;
    cudaLaunchAttribute at[1];
    at[0].id = cudaLaunchAttributeProgrammaticStreamSerialization;
    at[0].val.programmaticStreamSerializationAllowed = 1;
    cfg.attrs = at;
    cfg.numAttrs = 1;
    cudaLaunchKernelEx(&cfg, f, args...);
}

extern "C" void kernel_launch(void* const* d_in, const int* in_sizes, int n_in,
                              void* d_out, int out_size) {
    const float* ec    = (const float*)d_in[0];
    const float* mask  = (const float*)d_in[1];
    const int*   label = (const int*)d_in[2];
    const float* W1    = (const float*)d_in[3];
    const float* b1    = (const float*)d_in[4];
    const float* W2    = (const float*)d_in[5];
    const float* b2    = (const float*)d_in[6];
    const float* W3    = (const float*)d_in[7];
    const float* b3    = (const float*)d_in[8];
    float* out = (float*)d_out;

    const int loss_smem = Bn * ZPAD * (int)sizeof(float);
    static int inited = 0;
    if (!inited) {
        cudaFuncSetAttribute(loss_kernel,
                             cudaFuncAttributeMaxDynamicSharedMemorySize, loss_smem);
        inited = 1;
    }

    pool_kernel<<<dim3(Bn, 2), 256>>>(ec, mask);
    launch_pdl(gemm_bf16_kernel<1>, dim3(U1 / 64, Bn / 64, Cn), dim3(256), 0, W1, b1);
    launch_pdl(gemm_bf16_kernel<2>, dim3(U2 / 64, Bn / 64, Cn), dim3(256), 0, W2, b2);
    launch_pdl(gemm3_norm_kernel, dim3(Bn / 64, Cn), dim3(256), 0, W3, b3, out);
    launch_pdl(loss_kernel, dim3(Cn, Bn / 16), dim3(256), (size_t)loss_smem, out, label);
    launch_pdl(final_kernel, dim3(Cn), dim3(256), 0, out);
}

// round 13
// speedup vs baseline: 1.0182x; 1.0182x over previous
#include <cuda_runtime.h>
#include <math.h>
#include <stdint.h>

#define Bn 256
#define Mn 512
#define Dn 512
#define Cn 8
#define U1 512
#define U2 256
#define U3 128

// Scratch (device-code-only references)
__device__ float g_pooled[Bn * Dn];          // (B, D)
__device__ float g_h1[Cn * Bn * U1];         // (C, B, 512)
__device__ float g_h2[Cn * Bn * U2];         // (C, B, 256)
__device__ float g_term[Cn * Bn];            // per (c,b) loss term

// ---------------------------------------------------------------------------
// bf16 helpers
// ---------------------------------------------------------------------------
__device__ __forceinline__ uint32_t packbf(float lo, float hi) {
    uint32_t r;
    asm("cvt.rn.bf16x2.f32 %0, %1, %2;" : "=r"(r) : "f"(hi), "f"(lo));
    return r;
}
__device__ __forceinline__ void split2(float x0, float x1,
                                       uint32_t& h, uint32_t& l) {
    h = packbf(x0, x1);
    const float h0 = __uint_as_float(h << 16);
    const float h1 = __uint_as_float(h & 0xffff0000u);
    l = packbf(x0 - h0, x1 - h1);
}
__device__ __forceinline__ void mma16(float* d, const uint32_t* a, const uint32_t* b) {
    asm("mma.sync.aligned.m16n8k16.row.col.f32.bf16.bf16.f32 "
        "{%0,%1,%2,%3}, {%4,%5,%6,%7}, {%8,%9}, {%0,%1,%2,%3};"
        : "+f"(d[0]), "+f"(d[1]), "+f"(d[2]), "+f"(d[3])
        : "r"(a[0]), "r"(a[1]), "r"(a[2]), "r"(a[3]), "r"(b[0]), "r"(b[1]));
}

// ---------------------------------------------------------------------------
// 1) Masked sum pooling (proven version)
// ---------------------------------------------------------------------------
__global__ __launch_bounds__(256) void pool_kernel(const float* __restrict__ ec,
                                                   const float* __restrict__ mask) {
    const int b = blockIdx.x;
    const int dbase = blockIdx.y * 256;
    const int tid = threadIdx.x;

    __shared__ float keep[Mn];
    for (int i = tid; i < Mn; i += 256)
        keep[i] = (mask[b * Mn + i] == 0.0f) ? 1.0f : 0.0f;
    __syncthreads();

    const float* p = ec + ((size_t)b * Mn) * Dn + dbase + tid;
    float a0 = 0.f, a1 = 0.f, a2 = 0.f, a3 = 0.f;
#pragma unroll 4
    for (int m = 0; m < Mn; m += 4) {
        a0 = fmaf(p[(size_t)(m + 0) * Dn], keep[m + 0], a0);
        a1 = fmaf(p[(size_t)(m + 1) * Dn], keep[m + 1], a1);
        a2 = fmaf(p[(size_t)(m + 2) * Dn], keep[m + 2], a2);
        a3 = fmaf(p[(size_t)(m + 3) * Dn], keep[m + 3], a3);
    }
    g_pooled[b * Dn + dbase + tid] = (a0 + a1) + (a2 + a3);
}

// ---------------------------------------------------------------------------
// 2) Layers 1+2: bf16x3 tensor-core GEMM (proven round-11 version).
// ---------------------------------------------------------------------------
template <int LAYER>
__global__ __launch_bounds__(256) void gemm_bf16_kernel(
        const float* __restrict__ W, const float* __restrict__ bias) {
    constexpr int K = (LAYER == 1) ? Dn : U1;
    constexpr int N = (LAYER == 1) ? U1 : U2;
    constexpr bool AHASC = (LAYER != 1);
    const float* Aroot = (LAYER == 1) ? g_pooled : g_h1;
    float* Oroot       = (LAYER == 1) ? g_h1     : g_h2;

    const int c  = blockIdx.z;
    const int b0 = blockIdx.y * 64;
    const int n0 = blockIdx.x * 64;
    const int tid = threadIdx.x;
    const int lane = tid & 31;
    const int warp = tid >> 5;
    const int wm = warp >> 2;       // 0..1
    const int wn = warp & 3;        // 0..3
    const int g  = lane >> 2;       // 0..7
    const int tg = lane & 3;        // 0..3

    __shared__ uint32_t Ah[64][20], Al[64][20];   // [m][k2] packed bf16x2
    __shared__ uint32_t Wh[16][72], Wl[16][72];   // [k2][n] packed bf16x2

    float acc[2][2][4] = {};

    const float* Ag = Aroot + (AHASC ? (size_t)c * Bn * K : 0) + (size_t)b0 * K;
    const float* Wg = W + (size_t)c * K * N + n0;

    const int arow  = tid >> 2;          // 0..63
    const int acol2 = (tid & 3) * 4;     // packed col 0,4,8,12
    const int acolf = (tid & 3) * 8;     // float col
    const int wr2   = tid >> 4;          // 0..15 packed k row
    const int wc4   = (tid & 15) * 4;    // n col 0..60

    float4 gwa = *(const float4*)(Wg + (size_t)(2 * wr2) * N + wc4);
    float4 gwb = *(const float4*)(Wg + (size_t)(2 * wr2 + 1) * N + wc4);

    cudaGridDependencySynchronize();

    for (int k0 = 0; k0 < K; k0 += 32) {
        float4 ga0 = *(const float4*)(Ag + (size_t)arow * K + k0 + acolf);
        float4 ga1 = *(const float4*)(Ag + (size_t)arow * K + k0 + acolf + 4);

        __syncthreads();
        {
            uint32_t hp[4], lp[4];
            split2(ga0.x, ga0.y, hp[0], lp[0]);
            split2(ga0.z, ga0.w, hp[1], lp[1]);
            split2(ga1.x, ga1.y, hp[2], lp[2]);
            split2(ga1.z, ga1.w, hp[3], lp[3]);
            *(uint4*)&Ah[arow][acol2] = make_uint4(hp[0], hp[1], hp[2], hp[3]);
            *(uint4*)&Al[arow][acol2] = make_uint4(lp[0], lp[1], lp[2], lp[3]);
        }
        {
            uint32_t hw[4], lw[4];
            split2(gwa.x, gwb.x, hw[0], lw[0]);
            split2(gwa.y, gwb.y, hw[1], lw[1]);
            split2(gwa.z, gwb.z, hw[2], lw[2]);
            split2(gwa.w, gwb.w, hw[3], lw[3]);
            *(uint4*)&Wh[wr2][wc4] = make_uint4(hw[0], hw[1], hw[2], hw[3]);
            *(uint4*)&Wl[wr2][wc4] = make_uint4(lw[0], lw[1], lw[2], lw[3]);
        }
        __syncthreads();

        if (k0 + 32 < K) {
            gwa = *(const float4*)(Wg + (size_t)(k0 + 32 + 2 * wr2) * N + wc4);
            gwb = *(const float4*)(Wg + (size_t)(k0 + 32 + 2 * wr2 + 1) * N + wc4);
        }

#pragma unroll
        for (int kk = 0; kk < 2; kk++) {
            const int kb2 = kk * 8;
            uint32_t ah[2][4], al_[2][4], bh[2][2], bl[2][2];
#pragma unroll
            for (int mi = 0; mi < 2; mi++) {
                const int m = wm * 32 + mi * 16 + g;
                ah[mi][0]  = Ah[m][kb2 + tg];     ah[mi][1]  = Ah[m + 8][kb2 + tg];
                ah[mi][2]  = Ah[m][kb2 + tg + 4]; ah[mi][3]  = Ah[m + 8][kb2 + tg + 4];
                al_[mi][0] = Al[m][kb2 + tg];     al_[mi][1] = Al[m + 8][kb2 + tg];
                al_[mi][2] = Al[m][kb2 + tg + 4]; al_[mi][3] = Al[m + 8][kb2 + tg + 4];
            }
#pragma unroll
            for (int ni = 0; ni < 2; ni++) {
                const int n = wn * 16 + ni * 8 + g;
                bh[ni][0] = Wh[kb2 + tg][n]; bh[ni][1] = Wh[kb2 + tg + 4][n];
                bl[ni][0] = Wl[kb2 + tg][n]; bl[ni][1] = Wl[kb2 + tg + 4][n];
            }
#pragma unroll
            for (int mi = 0; mi < 2; mi++)
#pragma unroll
                for (int ni = 0; ni < 2; ni++) {
                    mma16(acc[mi][ni], ah[mi],  bh[ni]);
                    mma16(acc[mi][ni], ah[mi],  bl[ni]);
                    mma16(acc[mi][ni], al_[mi], bh[ni]);
                }
        }
    }

#pragma unroll
    for (int mi = 0; mi < 2; mi++) {
#pragma unroll
        for (int ni = 0; ni < 2; ni++) {
            const int ncol = n0 + wn * 16 + ni * 8 + tg * 2;
            const float bx = bias[c * N + ncol];
            const float by = bias[c * N + ncol + 1];
            const int r0 = b0 + wm * 32 + mi * 16 + g;
            float2 o0 = {fmaxf(acc[mi][ni][0] + bx, 0.f),
                         fmaxf(acc[mi][ni][1] + by, 0.f)};
            float2 o1 = {fmaxf(acc[mi][ni][2] + bx, 0.f),
                         fmaxf(acc[mi][ni][3] + by, 0.f)};
            *(float2*)(Oroot + ((size_t)(c * Bn + r0)) * N + ncol)     = o0;
            *(float2*)(Oroot + ((size_t)(c * Bn + r0 + 8)) * N + ncol) = o1;
        }
    }
}

// ---------------------------------------------------------------------------
// 3) Layer 3 + L2 normalize, bf16x3 MMA, 16-row tile (grid 128 blocks).
//    128 threads = 4 warps as 1m x 4n; warp tile 16(m) x 32(n).
//    Row ssq: intra-thread -> tg-quartet shuffle -> smem across 4 n-warps.
// ---------------------------------------------------------------------------
__global__ __launch_bounds__(128) void gemm3_norm_kernel(
        const float* __restrict__ W, const float* __restrict__ bias,
        float* __restrict__ zout) {
    constexpr int K = U2;   // 256
    constexpr int N = U3;   // 128
    const int b0 = blockIdx.x * 16;
    const int c  = blockIdx.y;
    const int tid = threadIdx.x;
    const int lane = tid & 31;
    const int wn = tid >> 5;        // 0..3 (n-warp)
    const int g  = lane >> 2;       // 0..7
    const int tg = lane & 3;        // 0..3

    __shared__ uint32_t Ah[16][20], Al[16][20];     // [m][k2]
    __shared__ uint32_t Wh[16][136], Wl[16][136];   // [k2][n], stride%32==8
    __shared__ float rowsq[16][4];                  // per-row ssq by n-warp

    float acc[4][4] = {};            // 4 n-frags x 4 regs

    const float* Ag = g_h2 + ((size_t)c * Bn + b0) * K;
    const float* Wg = W + (size_t)c * K * N;

    const int arow  = tid >> 3;          // 0..15
    const int acolf = (tid & 7) * 4;     // float col 0..28
    const int acol2 = (tid & 7) * 2;     // packed col 0..14
    const int wr2   = tid >> 3;          // 0..15 packed k row
    const int wc4   = (tid & 7) * 4;     // n col 0..28 (+32*ch chunks)

    // W k0=0 tile prefetch before the PDL gate (external input)
    float4 gwa[4], gwb[4];
#pragma unroll
    for (int ch = 0; ch < 4; ch++) {
        gwa[ch] = *(const float4*)(Wg + (size_t)(2 * wr2) * N + wc4 + 32 * ch);
        gwb[ch] = *(const float4*)(Wg + (size_t)(2 * wr2 + 1) * N + wc4 + 32 * ch);
    }

    cudaGridDependencySynchronize();    // gemm2 must be done before reading h2

    for (int k0 = 0; k0 < K; k0 += 32) {
        float4 ga = *(const float4*)(Ag + (size_t)arow * K + k0 + acolf);

        __syncthreads();
        {
            uint32_t h0, l0, h1, l1;
            split2(ga.x, ga.y, h0, l0);
            split2(ga.z, ga.w, h1, l1);
            *(uint2*)&Ah[arow][acol2] = make_uint2(h0, h1);
            *(uint2*)&Al[arow][acol2] = make_uint2(l0, l1);
        }
#pragma unroll
        for (int ch = 0; ch < 4; ch++) {
            uint32_t hw[4], lw[4];
            split2(gwa[ch].x, gwb[ch].x, hw[0], lw[0]);
            split2(gwa[ch].y, gwb[ch].y, hw[1], lw[1]);
            split2(gwa[ch].z, gwb[ch].z, hw[2], lw[2]);
            split2(gwa[ch].w, gwb[ch].w, hw[3], lw[3]);
            *(uint4*)&Wh[wr2][wc4 + 32 * ch] = make_uint4(hw[0], hw[1], hw[2], hw[3]);
            *(uint4*)&Wl[wr2][wc4 + 32 * ch] = make_uint4(lw[0], lw[1], lw[2], lw[3]);
        }
        __syncthreads();

        if (k0 + 32 < K) {
#pragma unroll
            for (int ch = 0; ch < 4; ch++) {
                gwa[ch] = *(const float4*)(Wg + (size_t)(k0 + 32 + 2 * wr2) * N + wc4 + 32 * ch);
                gwb[ch] = *(const float4*)(Wg + (size_t)(k0 + 32 + 2 * wr2 + 1) * N + wc4 + 32 * ch);
            }
        }

#pragma unroll
        for (int kk = 0; kk < 2; kk++) {
            const int kb2 = kk * 8;
            uint32_t ah[4], al_[4], bh[4][2], bl[4][2];
            ah[0]  = Ah[g][kb2 + tg];     ah[1]  = Ah[g + 8][kb2 + tg];
            ah[2]  = Ah[g][kb2 + tg + 4]; ah[3]  = Ah[g + 8][kb2 + tg + 4];
            al_[0] = Al[g][kb2 + tg];     al_[1] = Al[g + 8][kb2 + tg];
            al_[2] = Al[g][kb2 + tg + 4]; al_[3] = Al[g + 8][kb2 + tg + 4];
#pragma unroll
            for (int ni = 0; ni < 4; ni++) {
                const int n = wn * 32 + ni * 8 + g;
                bh[ni][0] = Wh[kb2 + tg][n]; bh[ni][1] = Wh[kb2 + tg + 4][n];
                bl[ni][0] = Wl[kb2 + tg][n]; bl[ni][1] = Wl[kb2 + tg + 4][n];
            }
#pragma unroll
            for (int ni = 0; ni < 4; ni++) {
                mma16(acc[ni], ah,  bh[ni]);
                mma16(acc[ni], ah,  bl[ni]);
                mma16(acc[ni], al_, bh[ni]);
            }
        }
    }

    // epilogue: bias + relu (into acc), per-row ssq
    float ss[2] = {0.f, 0.f};        // rows g, g+8
#pragma unroll
    for (int ni = 0; ni < 4; ni++) {
        const int ncol = wn * 32 + ni * 8 + tg * 2;
        const float bx = bias[c * N + ncol];
        const float by = bias[c * N + ncol + 1];
        float h0 = fmaxf(acc[ni][0] + bx, 0.f);
        float h1 = fmaxf(acc[ni][1] + by, 0.f);
        float h2 = fmaxf(acc[ni][2] + bx, 0.f);
        float h3 = fmaxf(acc[ni][3] + by, 0.f);
        acc[ni][0] = h0; acc[ni][1] = h1; acc[ni][2] = h2; acc[ni][3] = h3;
        ss[0] = fmaf(h0, h0, ss[0]);
        ss[0] = fmaf(h1, h1, ss[0]);
        ss[1] = fmaf(h2, h2, ss[1]);
        ss[1] = fmaf(h3, h3, ss[1]);
    }
#pragma unroll
    for (int p = 0; p < 2; p++) {
        ss[p] += __shfl_xor_sync(0xffffffffu, ss[p], 1);
        ss[p] += __shfl_xor_sync(0xffffffffu, ss[p], 2);
    }
    if (tg == 0) {
        rowsq[g][wn]     = ss[0];
        rowsq[g + 8][wn] = ss[1];
    }
    __syncthreads();

    const float t0 = ((rowsq[g][0] + rowsq[g][1]) + (rowsq[g][2] + rowsq[g][3]));
    const float t1 = ((rowsq[g + 8][0] + rowsq[g + 8][1]) + (rowsq[g + 8][2] + rowsq[g + 8][3]));
    const float r0 = rsqrtf(fmaxf(t0, 1e-12f));
    const float r1 = rsqrtf(fmaxf(t1, 1e-12f));
#pragma unroll
    for (int ni = 0; ni < 4; ni++) {
        const int ncol = wn * 32 + ni * 8 + tg * 2;
        float2 o0 = {acc[ni][0] * r0, acc[ni][1] * r0};
        float2 o1 = {acc[ni][2] * r1, acc[ni][3] * r1};
        *(float2*)(zout + ((size_t)(c * Bn + b0 + g)) * N + ncol)     = o0;
        *(float2*)(zout + ((size_t)(c * Bn + b0 + g + 8)) * N + ncol) = o1;
    }
}

// ---------------------------------------------------------------------------
// 4) Per-(c,b) contrastive term. grid (C, 16); 8 warps, 2 rows per warp.
// ---------------------------------------------------------------------------
#define ZPAD 132
__global__ __launch_bounds__(256) void loss_kernel(const float* __restrict__ z,
                                                   const int* __restrict__ label) {
    extern __shared__ float zs[];          // [256][ZPAD]
    __shared__ int slab[Bn];
    __shared__ int wsum[8];

    const int c = blockIdx.x;
    const int tid = threadIdx.x;
    const int lane = tid & 31;
    const int warp = tid >> 5;

    const int myl = label[tid * Cn + c];
    slab[tid] = myl;
    int s = myl;
#pragma unroll
    for (int o = 16; o; o >>= 1) s += __shfl_xor_sync(0xffffffffu, s, o);
    if (lane == 0) wsum[warp] = s;

    cudaGridDependencySynchronize();

    const float* zc = z + (size_t)c * Bn * U3;
    for (int idx = tid; idx < Bn * U3 / 4; idx += 256) {
        const int row = idx >> 5;
        const int c4 = idx & 31;
        float4 v = *(const float4*)(zc + (size_t)row * U3 + c4 * 4);
        *(float4*)&zs[row * ZPAD + c4 * 4] = v;
    }
    __syncthreads();
    int nump = 0;
#pragma unroll
    for (int i = 0; i < 8; i++) nump += wsum[i];

    const int bb = blockIdx.y * 16 + warp * 2;

    int lb[2];
    const float* zb[2];
#pragma unroll
    for (int i = 0; i < 2; i++) {
        lb[i] = slab[bb + i];
        zb[i] = &zs[(bb + i) * ZPAD];
    }

    float es[2] = {0.f, 0.f};
    float ps[2] = {0.f, 0.f};

#pragma unroll
    for (int kk = 0; kk < 8; kk++) {
        const int k = kk * 32 + lane;
        const float* zk = &zs[k * ZPAD];
        float s0 = 0.f, s1 = 0.f;
#pragma unroll
        for (int j = 0; j < U3; j += 4) {
            float4 x  = *(const float4*)(zk + j);
            float4 a0 = *(const float4*)(zb[0] + j);
            float4 a1 = *(const float4*)(zb[1] + j);
            s0 = fmaf(a0.x, x.x, s0); s0 = fmaf(a0.y, x.y, s0);
            s0 = fmaf(a0.z, x.z, s0); s0 = fmaf(a0.w, x.w, s0);
            s1 = fmaf(a1.x, x.x, s1); s1 = fmaf(a1.y, x.y, s1);
            s1 = fmaf(a1.z, x.z, s1); s1 = fmaf(a1.w, x.w, s1);
        }
        const int sk = slab[k];
        float sv[2] = {s0, s1};
#pragma unroll
        for (int i = 0; i < 2; i++) {
            const float ipv = (k == bb + i) ? 0.0f : sv[i] * 2.0f;  // /TEMP
            es[i] += __expf(ipv);
            if (sk == lb[i]) ps[i] += ipv;
        }
    }

#pragma unroll
    for (int i = 0; i < 2; i++) {
#pragma unroll
        for (int o = 16; o; o >>= 1) {
            es[i] += __shfl_xor_sync(0xffffffffu, es[i], o);
            ps[i] += __shfl_xor_sync(0xffffffffu, ps[i], o);
        }
    }
    if (lane == 0) {
#pragma unroll
        for (int i = 0; i < 2; i++) {
            const int numv = lb[i] ? nump : (Bn - nump);
            g_term[c * Bn + bb + i] = ps[i] / (float)numv - logf(es[i]);
        }
    }
}

// ---------------------------------------------------------------------------
// 5) Reduce terms -> losses[c]
// ---------------------------------------------------------------------------
__global__ __launch_bounds__(256) void final_kernel(float* __restrict__ out) {
    __shared__ float red[Bn];
    const int c = blockIdx.x;
    const int tid = threadIdx.x;
    cudaGridDependencySynchronize();
    red[tid] = g_term[c * Bn + tid];
    __syncthreads();
    for (int s = 128; s; s >>= 1) {
        if (tid < s) red[tid] += red[tid + s];
        __syncthreads();
    }
    if (tid == 0) out[(size_t)Cn * Bn * U3 + c] = -red[0];
}

// ---------------------------------------------------------------------------
// Launch with PDL on the capture stream.
// ---------------------------------------------------------------------------
template <typename F, typename... Args>
static void launch_pdl(F f, dim3 grid, dim3 block, size_t smem, Args... args) {
    cudaLaunchConfig_t cfg = {};
    cfg.gridDim = grid;
    cfg.blockDim = block;
    cfg.dynamicSmemBytes = smem;
    cfg.stream = 0;
    cudaLaunchAttribute at[1];
    at[0].id = cudaLaunchAttributeProgrammaticStreamSerialization;
    at[0].val.programmaticStreamSerializationAllowed = 1;
    cfg.attrs = at;
    cfg.numAttrs = 1;
    cudaLaunchKernelEx(&cfg, f, args...);
}

extern "C" void kernel_launch(void* const* d_in, const int* in_sizes, int n_in,
                              void* d_out, int out_size) {
    const float* ec    = (const float*)d_in[0];
    const float* mask  = (const float*)d_in[1];
    const int*   label = (const int*)d_in[2];
    const float* W1    = (const float*)d_in[3];
    const float* b1    = (const float*)d_in[4];
    const float* W2    = (const float*)d_in[5];
    const float* b2    = (const float*)d_in[6];
    const float* W3    = (const float*)d_in[7];
    const float* b3    = (const float*)d_in[8];
    float* out = (float*)d_out;

    const int loss_smem = Bn * ZPAD * (int)sizeof(float);
    static int inited = 0;
    if (!inited) {
        cudaFuncSetAttribute(loss_kernel,
                             cudaFuncAttributeMaxDynamicSharedMemorySize, loss_smem);
        inited = 1;
    }

    pool_kernel<<<dim3(Bn, 2), 256>>>(ec, mask);
    launch_pdl(gemm_bf16_kernel<1>, dim3(U1 / 64, Bn / 64, Cn), dim3(256), 0, W1, b1);
    launch_pdl(gemm_bf16_kernel<2>, dim3(U2 / 64, Bn / 64, Cn), dim3(256), 0, W2, b2);
    launch_pdl(gemm3_norm_kernel, dim3(Bn / 16, Cn), dim3(128), 0, W3, b3, out);
    launch_pdl(loss_kernel, dim3(Cn, Bn / 16), dim3(256), (size_t)loss_smem, out, label);
    launch_pdl(final_kernel, dim3(Cn), dim3(256), 0, out);
}

// round 14
// speedup vs baseline: 1.0295x; 1.0110x over previous
#include <cuda_runtime.h>
#include <math.h>
#include <stdint.h>

#define Bn 256
#define Mn 512
#define Dn 512
#define Cn 8
#define U1 512
#define U2 256
#define U3 128

// Scratch (device-code-only references)
__device__ float g_pooled[Bn * Dn];          // (B, D)
__device__ float g_h1[Cn * Bn * U1];         // (C, B, 512)
__device__ float g_h2[Cn * Bn * U2];         // (C, B, 256)
__device__ float g_term[Cn * Bn];            // per (c,b) loss term

// ---------------------------------------------------------------------------
// bf16 helpers
// ---------------------------------------------------------------------------
__device__ __forceinline__ uint32_t packbf(float lo, float hi) {
    uint32_t r;
    asm("cvt.rn.bf16x2.f32 %0, %1, %2;" : "=r"(r) : "f"(hi), "f"(lo));
    return r;
}
__device__ __forceinline__ void split2(float x0, float x1,
                                       uint32_t& h, uint32_t& l) {
    h = packbf(x0, x1);
    const float h0 = __uint_as_float(h << 16);
    const float h1 = __uint_as_float(h & 0xffff0000u);
    l = packbf(x0 - h0, x1 - h1);
}
__device__ __forceinline__ void mma16(float* d, const uint32_t* a, const uint32_t* b) {
    asm("mma.sync.aligned.m16n8k16.row.col.f32.bf16.bf16.f32 "
        "{%0,%1,%2,%3}, {%4,%5,%6,%7}, {%8,%9}, {%0,%1,%2,%3};"
        : "+f"(d[0]), "+f"(d[1]), "+f"(d[2]), "+f"(d[3])
        : "r"(a[0]), "r"(a[1]), "r"(a[2]), "r"(a[3]), "r"(b[0]), "r"(b[1]));
}

// ---------------------------------------------------------------------------
// 1) Masked sum pooling (proven version)
// ---------------------------------------------------------------------------
__global__ __launch_bounds__(256) void pool_kernel(const float* __restrict__ ec,
                                                   const float* __restrict__ mask) {
    const int b = blockIdx.x;
    const int dbase = blockIdx.y * 256;
    const int tid = threadIdx.x;

    __shared__ float keep[Mn];
    for (int i = tid; i < Mn; i += 256)
        keep[i] = (mask[b * Mn + i] == 0.0f) ? 1.0f : 0.0f;
    __syncthreads();

    const float* p = ec + ((size_t)b * Mn) * Dn + dbase + tid;
    float a0 = 0.f, a1 = 0.f, a2 = 0.f, a3 = 0.f;
#pragma unroll 4
    for (int m = 0; m < Mn; m += 4) {
        a0 = fmaf(p[(size_t)(m + 0) * Dn], keep[m + 0], a0);
        a1 = fmaf(p[(size_t)(m + 1) * Dn], keep[m + 1], a1);
        a2 = fmaf(p[(size_t)(m + 2) * Dn], keep[m + 2], a2);
        a3 = fmaf(p[(size_t)(m + 3) * Dn], keep[m + 3], a3);
    }
    g_pooled[b * Dn + dbase + tid] = (a0 + a1) + (a2 + a3);
}

// ---------------------------------------------------------------------------
// 2) Layers 1+2: bf16x3 tensor-core GEMM (proven round-11 version).
// ---------------------------------------------------------------------------
template <int LAYER>
__global__ __launch_bounds__(256) void gemm_bf16_kernel(
        const float* __restrict__ W, const float* __restrict__ bias) {
    constexpr int K = (LAYER == 1) ? Dn : U1;
    constexpr int N = (LAYER == 1) ? U1 : U2;
    constexpr bool AHASC = (LAYER != 1);
    const float* Aroot = (LAYER == 1) ? g_pooled : g_h1;
    float* Oroot       = (LAYER == 1) ? g_h1     : g_h2;

    const int c  = blockIdx.z;
    const int b0 = blockIdx.y * 64;
    const int n0 = blockIdx.x * 64;
    const int tid = threadIdx.x;
    const int lane = tid & 31;
    const int warp = tid >> 5;
    const int wm = warp >> 2;       // 0..1
    const int wn = warp & 3;        // 0..3
    const int g  = lane >> 2;       // 0..7
    const int tg = lane & 3;        // 0..3

    __shared__ uint32_t Ah[64][20], Al[64][20];   // [m][k2] packed bf16x2
    __shared__ uint32_t Wh[16][72], Wl[16][72];   // [k2][n] packed bf16x2

    float acc[2][2][4] = {};

    const float* Ag = Aroot + (AHASC ? (size_t)c * Bn * K : 0) + (size_t)b0 * K;
    const float* Wg = W + (size_t)c * K * N + n0;

    const int arow  = tid >> 2;          // 0..63
    const int acol2 = (tid & 3) * 4;     // packed col 0,4,8,12
    const int acolf = (tid & 3) * 8;     // float col
    const int wr2   = tid >> 4;          // 0..15 packed k row
    const int wc4   = (tid & 15) * 4;    // n col 0..60

    float4 gwa = *(const float4*)(Wg + (size_t)(2 * wr2) * N + wc4);
    float4 gwb = *(const float4*)(Wg + (size_t)(2 * wr2 + 1) * N + wc4);

    cudaGridDependencySynchronize();

    for (int k0 = 0; k0 < K; k0 += 32) {
        float4 ga0 = *(const float4*)(Ag + (size_t)arow * K + k0 + acolf);
        float4 ga1 = *(const float4*)(Ag + (size_t)arow * K + k0 + acolf + 4);

        __syncthreads();
        {
            uint32_t hp[4], lp[4];
            split2(ga0.x, ga0.y, hp[0], lp[0]);
            split2(ga0.z, ga0.w, hp[1], lp[1]);
            split2(ga1.x, ga1.y, hp[2], lp[2]);
            split2(ga1.z, ga1.w, hp[3], lp[3]);
            *(uint4*)&Ah[arow][acol2] = make_uint4(hp[0], hp[1], hp[2], hp[3]);
            *(uint4*)&Al[arow][acol2] = make_uint4(lp[0], lp[1], lp[2], lp[3]);
        }
        {
            uint32_t hw[4], lw[4];
            split2(gwa.x, gwb.x, hw[0], lw[0]);
            split2(gwa.y, gwb.y, hw[1], lw[1]);
            split2(gwa.z, gwb.z, hw[2], lw[2]);
            split2(gwa.w, gwb.w, hw[3], lw[3]);
            *(uint4*)&Wh[wr2][wc4] = make_uint4(hw[0], hw[1], hw[2], hw[3]);
            *(uint4*)&Wl[wr2][wc4] = make_uint4(lw[0], lw[1], lw[2], lw[3]);
        }
        __syncthreads();

        if (k0 + 32 < K) {
            gwa = *(const float4*)(Wg + (size_t)(k0 + 32 + 2 * wr2) * N + wc4);
            gwb = *(const float4*)(Wg + (size_t)(k0 + 32 + 2 * wr2 + 1) * N + wc4);
        }

#pragma unroll
        for (int kk = 0; kk < 2; kk++) {
            const int kb2 = kk * 8;
            uint32_t ah[2][4], al_[2][4], bh[2][2], bl[2][2];
#pragma unroll
            for (int mi = 0; mi < 2; mi++) {
                const int m = wm * 32 + mi * 16 + g;
                ah[mi][0]  = Ah[m][kb2 + tg];     ah[mi][1]  = Ah[m + 8][kb2 + tg];
                ah[mi][2]  = Ah[m][kb2 + tg + 4]; ah[mi][3]  = Ah[m + 8][kb2 + tg + 4];
                al_[mi][0] = Al[m][kb2 + tg];     al_[mi][1] = Al[m + 8][kb2 + tg];
                al_[mi][2] = Al[m][kb2 + tg + 4]; al_[mi][3] = Al[m + 8][kb2 + tg + 4];
            }
#pragma unroll
            for (int ni = 0; ni < 2; ni++) {
                const int n = wn * 16 + ni * 8 + g;
                bh[ni][0] = Wh[kb2 + tg][n]; bh[ni][1] = Wh[kb2 + tg + 4][n];
                bl[ni][0] = Wl[kb2 + tg][n]; bl[ni][1] = Wl[kb2 + tg + 4][n];
            }
#pragma unroll
            for (int mi = 0; mi < 2; mi++)
#pragma unroll
                for (int ni = 0; ni < 2; ni++) {
                    mma16(acc[mi][ni], ah[mi],  bh[ni]);
                    mma16(acc[mi][ni], ah[mi],  bl[ni]);
                    mma16(acc[mi][ni], al_[mi], bh[ni]);
                }
        }
    }

#pragma unroll
    for (int mi = 0; mi < 2; mi++) {
#pragma unroll
        for (int ni = 0; ni < 2; ni++) {
            const int ncol = n0 + wn * 16 + ni * 8 + tg * 2;
            const float bx = bias[c * N + ncol];
            const float by = bias[c * N + ncol + 1];
            const int r0 = b0 + wm * 32 + mi * 16 + g;
            float2 o0 = {fmaxf(acc[mi][ni][0] + bx, 0.f),
                         fmaxf(acc[mi][ni][1] + by, 0.f)};
            float2 o1 = {fmaxf(acc[mi][ni][2] + bx, 0.f),
                         fmaxf(acc[mi][ni][3] + by, 0.f)};
            *(float2*)(Oroot + ((size_t)(c * Bn + r0)) * N + ncol)     = o0;
            *(float2*)(Oroot + ((size_t)(c * Bn + r0 + 8)) * N + ncol) = o1;
        }
    }
}

// ---------------------------------------------------------------------------
// 3) Layer 3 + L2 normalize, bf16x3 MMA, bulk-staged.
//    16-row tile, grid (16, 8) = 128 blocks, 256 threads = 8 n-warps,
//    warp tile 16(m) x 16(n). FULL W3[c] (256x128) staged into dynamic smem
//    BEFORE the PDL gate (W is an external input -> overlaps gemm2 tail).
//    Post-gate: stage A (16x256), one sync, 96 MMAs/warp, epilogue.
//    smem (uint32): Wh[128][136], Wl[128][136], Ah[16][132], Al[16][132].
// ---------------------------------------------------------------------------
#define G3_WH 0
#define G3_WL (128 * 136)
#define G3_AH (2 * 128 * 136)
#define G3_AL (2 * 128 * 136 + 16 * 132)
#define G3_SMEM ((2 * 128 * 136 + 2 * 16 * 132) * 4)

__global__ __launch_bounds__(256) void gemm3_norm_kernel(
        const float* __restrict__ W, const float* __restrict__ bias,
        float* __restrict__ zout) {
    constexpr int K = U2;   // 256
    constexpr int N = U3;   // 128
    const int b0 = blockIdx.x * 16;
    const int c  = blockIdx.y;
    const int tid = threadIdx.x;
    const int lane = tid & 31;
    const int wn = tid >> 5;        // 0..7 (n-warp)
    const int g  = lane >> 2;       // 0..7
    const int tg = lane & 3;        // 0..3

    extern __shared__ uint32_t sm[];
    uint32_t* Wh = sm + G3_WH;      // [128][136]
    uint32_t* Wl = sm + G3_WL;
    uint32_t* Ah = sm + G3_AH;      // [16][132]
    uint32_t* Al = sm + G3_AL;
    __shared__ float rowsq[16][8];

    const float* Ag = g_h2 + ((size_t)c * Bn + b0) * K;
    const float* Wg = W + (size_t)c * K * N;

    // ---- Pre-gate: stage FULL W (external input; overlaps producer) ----
    // thread handles k2row = i>>4, n-chunk nn = i&15 (4 n per chunk)
#pragma unroll
    for (int it = 0; it < 8; it++) {
        const int i = tid + it * 256;       // 0..2047
        const int k2r = i >> 4;             // 0..127
        const int nn4 = (i & 15) * 4;       // 0..60... n col (x4)
        float4 wa = *(const float4*)(Wg + (size_t)(2 * k2r) * N + nn4 * 2);
        float4 wb = *(const float4*)(Wg + (size_t)(2 * k2r + 1) * N + nn4 * 2);
        float4 wc = *(const float4*)(Wg + (size_t)(2 * k2r) * N + nn4 * 2 + 4);
        float4 wd = *(const float4*)(Wg + (size_t)(2 * k2r + 1) * N + nn4 * 2 + 4);
        uint32_t h[8], l[8];
        split2(wa.x, wb.x, h[0], l[0]);
        split2(wa.y, wb.y, h[1], l[1]);
        split2(wa.z, wb.z, h[2], l[2]);
        split2(wa.w, wb.w, h[3], l[3]);
        split2(wc.x, wd.x, h[4], l[4]);
        split2(wc.y, wd.y, h[5], l[5]);
        split2(wc.z, wd.z, h[6], l[6]);
        split2(wc.w, wd.w, h[7], l[7]);
        *(uint4*)&Wh[k2r * 136 + nn4 * 2]     = make_uint4(h[0], h[1], h[2], h[3]);
        *(uint4*)&Wh[k2r * 136 + nn4 * 2 + 4] = make_uint4(h[4], h[5], h[6], h[7]);
        *(uint4*)&Wl[k2r * 136 + nn4 * 2]     = make_uint4(l[0], l[1], l[2], l[3]);
        *(uint4*)&Wl[k2r * 136 + nn4 * 2 + 4] = make_uint4(l[4], l[5], l[6], l[7]);
    }

    cudaGridDependencySynchronize();    // gemm2 must be done before reading h2

    // ---- Post-gate: stage A (16 x 256) ----
#pragma unroll
    for (int it = 0; it < 4; it++) {
        const int i = tid + it * 256;       // 0..1023 float4 index
        const int row = i >> 6;             // 0..15
        const int c4 = (i & 63) * 4;        // float col 0..252
        float4 a = *(const float4*)(Ag + (size_t)row * K + c4);
        uint32_t h0, l0, h1, l1;
        split2(a.x, a.y, h0, l0);
        split2(a.z, a.w, h1, l1);
        *(uint2*)&Ah[row * 132 + (c4 >> 1)] = make_uint2(h0, h1);
        *(uint2*)&Al[row * 132 + (c4 >> 1)] = make_uint2(l0, l1);
    }
    __syncthreads();

    // ---- MMA: 16 k-steps, 2 n-frags per warp ----
    float acc[2][4] = {};
#pragma unroll
    for (int step = 0; step < 16; step++) {
        const int kb2 = step * 8;
        uint32_t ah[4], al_[4], bh[2][2], bl[2][2];
        ah[0]  = Ah[g * 132 + kb2 + tg];     ah[1]  = Ah[(g + 8) * 132 + kb2 + tg];
        ah[2]  = Ah[g * 132 + kb2 + tg + 4]; ah[3]  = Ah[(g + 8) * 132 + kb2 + tg + 4];
        al_[0] = Al[g * 132 + kb2 + tg];     al_[1] = Al[(g + 8) * 132 + kb2 + tg];
        al_[2] = Al[g * 132 + kb2 + tg + 4]; al_[3] = Al[(g + 8) * 132 + kb2 + tg + 4];
#pragma unroll
        for (int ni = 0; ni < 2; ni++) {
            const int n = wn * 16 + ni * 8 + g;
            bh[ni][0] = Wh[(kb2 + tg) * 136 + n]; bh[ni][1] = Wh[(kb2 + tg + 4) * 136 + n];
            bl[ni][0] = Wl[(kb2 + tg) * 136 + n]; bl[ni][1] = Wl[(kb2 + tg + 4) * 136 + n];
        }
#pragma unroll
        for (int ni = 0; ni < 2; ni++) {
            mma16(acc[ni], ah,  bh[ni]);
            mma16(acc[ni], ah,  bl[ni]);
            mma16(acc[ni], al_, bh[ni]);
        }
    }

    // ---- Epilogue: bias + relu, row ssq, normalize, store ----
    float ss[2] = {0.f, 0.f};        // rows g, g+8
#pragma unroll
    for (int ni = 0; ni < 2; ni++) {
        const int ncol = wn * 16 + ni * 8 + tg * 2;
        const float bx = bias[c * N + ncol];
        const float by = bias[c * N + ncol + 1];
        float h0 = fmaxf(acc[ni][0] + bx, 0.f);
        float h1 = fmaxf(acc[ni][1] + by, 0.f);
        float h2 = fmaxf(acc[ni][2] + bx, 0.f);
        float h3 = fmaxf(acc[ni][3] + by, 0.f);
        acc[ni][0] = h0; acc[ni][1] = h1; acc[ni][2] = h2; acc[ni][3] = h3;
        ss[0] = fmaf(h0, h0, ss[0]);
        ss[0] = fmaf(h1, h1, ss[0]);
        ss[1] = fmaf(h2, h2, ss[1]);
        ss[1] = fmaf(h3, h3, ss[1]);
    }
#pragma unroll
    for (int p = 0; p < 2; p++) {
        ss[p] += __shfl_xor_sync(0xffffffffu, ss[p], 1);
        ss[p] += __shfl_xor_sync(0xffffffffu, ss[p], 2);
    }
    if (tg == 0) {
        rowsq[g][wn]     = ss[0];
        rowsq[g + 8][wn] = ss[1];
    }
    __syncthreads();

    float t0 = 0.f, t1 = 0.f;
#pragma unroll
    for (int q = 0; q < 8; q++) { t0 += rowsq[g][q]; t1 += rowsq[g + 8][q]; }
    const float r0 = rsqrtf(fmaxf(t0, 1e-12f));
    const float r1 = rsqrtf(fmaxf(t1, 1e-12f));
#pragma unroll
    for (int ni = 0; ni < 2; ni++) {
        const int ncol = wn * 16 + ni * 8 + tg * 2;
        float2 o0 = {acc[ni][0] * r0, acc[ni][1] * r0};
        float2 o1 = {acc[ni][2] * r1, acc[ni][3] * r1};
        *(float2*)(zout + ((size_t)(c * Bn + b0 + g)) * N + ncol)     = o0;
        *(float2*)(zout + ((size_t)(c * Bn + b0 + g + 8)) * N + ncol) = o1;
    }
}

// ---------------------------------------------------------------------------
// 4) Per-(c,b) contrastive term. grid (C, 16); 8 warps, 2 rows per warp.
// ---------------------------------------------------------------------------
#define ZPAD 132
__global__ __launch_bounds__(256) void loss_kernel(const float* __restrict__ z,
                                                   const int* __restrict__ label) {
    extern __shared__ float zs[];          // [256][ZPAD]
    __shared__ int slab[Bn];
    __shared__ int wsum[8];

    const int c = blockIdx.x;
    const int tid = threadIdx.x;
    const int lane = tid & 31;
    const int warp = tid >> 5;

    const int myl = label[tid * Cn + c];
    slab[tid] = myl;
    int s = myl;
#pragma unroll
    for (int o = 16; o; o >>= 1) s += __shfl_xor_sync(0xffffffffu, s, o);
    if (lane == 0) wsum[warp] = s;

    cudaGridDependencySynchronize();

    const float* zc = z + (size_t)c * Bn * U3;
    for (int idx = tid; idx < Bn * U3 / 4; idx += 256) {
        const int row = idx >> 5;
        const int c4 = idx & 31;
        float4 v = *(const float4*)(zc + (size_t)row * U3 + c4 * 4);
        *(float4*)&zs[row * ZPAD + c4 * 4] = v;
    }
    __syncthreads();
    int nump = 0;
#pragma unroll
    for (int i = 0; i < 8; i++) nump += wsum[i];

    const int bb = blockIdx.y * 16 + warp * 2;

    int lb[2];
    const float* zb[2];
#pragma unroll
    for (int i = 0; i < 2; i++) {
        lb[i] = slab[bb + i];
        zb[i] = &zs[(bb + i) * ZPAD];
    }

    float es[2] = {0.f, 0.f};
    float ps[2] = {0.f, 0.f};

#pragma unroll
    for (int kk = 0; kk < 8; kk++) {
        const int k = kk * 32 + lane;
        const float* zk = &zs[k * ZPAD];
        float s0 = 0.f, s1 = 0.f;
#pragma unroll
        for (int j = 0; j < U3; j += 4) {
            float4 x  = *(const float4*)(zk + j);
            float4 a0 = *(const float4*)(zb[0] + j);
            float4 a1 = *(const float4*)(zb[1] + j);
            s0 = fmaf(a0.x, x.x, s0); s0 = fmaf(a0.y, x.y, s0);
            s0 = fmaf(a0.z, x.z, s0); s0 = fmaf(a0.w, x.w, s0);
            s1 = fmaf(a1.x, x.x, s1); s1 = fmaf(a1.y, x.y, s1);
            s1 = fmaf(a1.z, x.z, s1); s1 = fmaf(a1.w, x.w, s1);
        }
        const int sk = slab[k];
        float sv[2] = {s0, s1};
#pragma unroll
        for (int i = 0; i < 2; i++) {
            const float ipv = (k == bb + i) ? 0.0f : sv[i] * 2.0f;  // /TEMP
            es[i] += __expf(ipv);
            if (sk == lb[i]) ps[i] += ipv;
        }
    }

#pragma unroll
    for (int i = 0; i < 2; i++) {
#pragma unroll
        for (int o = 16; o; o >>= 1) {
            es[i] += __shfl_xor_sync(0xffffffffu, es[i], o);
            ps[i] += __shfl_xor_sync(0xffffffffu, ps[i], o);
        }
    }
    if (lane == 0) {
#pragma unroll
        for (int i = 0; i < 2; i++) {
            const int numv = lb[i] ? nump : (Bn - nump);
            g_term[c * Bn + bb + i] = ps[i] / (float)numv - logf(es[i]);
        }
    }
}

// ---------------------------------------------------------------------------
// 5) Reduce terms -> losses[c]
// ---------------------------------------------------------------------------
__global__ __launch_bounds__(256) void final_kernel(float* __restrict__ out) {
    __shared__ float red[Bn];
    const int c = blockIdx.x;
    const int tid = threadIdx.x;
    cudaGridDependencySynchronize();
    red[tid] = g_term[c * Bn + tid];
    __syncthreads();
    for (int s = 128; s; s >>= 1) {
        if (tid < s) red[tid] += red[tid + s];
        __syncthreads();
    }
    if (tid == 0) out[(size_t)Cn * Bn * U3 + c] = -red[0];
}

// ---------------------------------------------------------------------------
// Launch with PDL on the capture stream.
// ---------------------------------------------------------------------------
template <typename F, typename... Args>
static void launch_pdl(F f, dim3 grid, dim3 block, size_t smem, Args... args) {
    cudaLaunchConfig_t cfg = {};
    cfg.gridDim = grid;
    cfg.blockDim = block;
    cfg.dynamicSmemBytes = smem;
    cfg.stream = 0;
    cudaLaunchAttribute at[1];
    at[0].id = cudaLaunchAttributeProgrammaticStreamSerialization;
    at[0].val.programmaticStreamSerializationAllowed = 1;
    cfg.attrs = at;
    cfg.numAttrs = 1;
    cudaLaunchKernelEx(&cfg, f, args...);
}

extern "C" void kernel_launch(void* const* d_in, const int* in_sizes, int n_in,
                              void* d_out, int out_size) {
    const float* ec    = (const float*)d_in[0];
    const float* mask  = (const float*)d_in[1];
    const int*   label = (const int*)d_in[2];
    const float* W1    = (const float*)d_in[3];
    const float* b1    = (const float*)d_in[4];
    const float* W2    = (const float*)d_in[5];
    const float* b2    = (const float*)d_in[6];
    const float* W3    = (const float*)d_in[7];
    const float* b3    = (const float*)d_in[8];
    float* out = (float*)d_out;

    const int loss_smem = Bn * ZPAD * (int)sizeof(float);
    static int inited = 0;
    if (!inited) {
        cudaFuncSetAttribute(loss_kernel,
                             cudaFuncAttributeMaxDynamicSharedMemorySize, loss_smem);
        cudaFuncSetAttribute(gemm3_norm_kernel,
                             cudaFuncAttributeMaxDynamicSharedMemorySize, G3_SMEM);
        inited = 1;
    }

    pool_kernel<<<dim3(Bn, 2), 256>>>(ec, mask);
    launch_pdl(gemm_bf16_kernel<1>, dim3(U1 / 64, Bn / 64, Cn), dim3(256), 0, W1, b1);
    launch_pdl(gemm_bf16_kernel<2>, dim3(U2 / 64, Bn / 64, Cn), dim3(256), 0, W2, b2);
    launch_pdl(gemm3_norm_kernel, dim3(Bn / 16, Cn), dim3(256), (size_t)G3_SMEM, W3, b3, out);
    launch_pdl(loss_kernel, dim3(Cn, Bn / 16), dim3(256), (size_t)loss_smem, out, label);
    launch_pdl(final_kernel, dim3(Cn), dim3(256), 0, out);
}

// round 15
// speedup vs baseline: 1.0552x; 1.0250x over previous
#include <cuda_runtime.h>
#include <math.h>
#include <stdint.h>

#define Bn 256
#define Mn 512
#define Dn 512
#define Cn 8
#define U1 512
#define U2 256
#define U3 128

// Scratch (device-code-only references)
__device__ float g_pooled[Bn * Dn];          // (B, D)
__device__ float g_h1[Cn * Bn * U1];         // (C, B, 512)
__device__ float g_h2[Cn * Bn * U2];         // (C, B, 256)
__device__ float g_term[Cn * Bn];            // per (c,b) loss term

// ---------------------------------------------------------------------------
// bf16 helpers
// ---------------------------------------------------------------------------
__device__ __forceinline__ uint32_t packbf(float lo, float hi) {
    uint32_t r;
    asm("cvt.rn.bf16x2.f32 %0, %1, %2;" : "=r"(r) : "f"(hi), "f"(lo));
    return r;
}
__device__ __forceinline__ void split2(float x0, float x1,
                                       uint32_t& h, uint32_t& l) {
    h = packbf(x0, x1);
    const float h0 = __uint_as_float(h << 16);
    const float h1 = __uint_as_float(h & 0xffff0000u);
    l = packbf(x0 - h0, x1 - h1);
}
__device__ __forceinline__ void mma16(float* d, const uint32_t* a, const uint32_t* b) {
    asm("mma.sync.aligned.m16n8k16.row.col.f32.bf16.bf16.f32 "
        "{%0,%1,%2,%3}, {%4,%5,%6,%7}, {%8,%9}, {%0,%1,%2,%3};"
        : "+f"(d[0]), "+f"(d[1]), "+f"(d[2]), "+f"(d[3])
        : "r"(a[0]), "r"(a[1]), "r"(a[2]), "r"(a[3]), "r"(b[0]), "r"(b[1]));
}

// ---------------------------------------------------------------------------
// 1) Masked sum pooling with LDG.128. grid (Bn, 2), 256 threads:
//    d4 = tid&63 (float4 over the 256-float d-slice), mq = tid>>6 (m-quarter
//    of 128 rows each). Fixed-order smem combine -> deterministic.
// ---------------------------------------------------------------------------
__global__ __launch_bounds__(256) void pool_kernel(const float* __restrict__ ec,
                                                   const float* __restrict__ mask) {
    const int b = blockIdx.x;
    const int dbase = blockIdx.y * 256;
    const int tid = threadIdx.x;
    const int d4 = tid & 63;        // 0..63 (float4 within 256-float slice)
    const int mq = tid >> 6;        // 0..3 (m-quarter)

    __shared__ float keep[Mn];
    __shared__ float4 part[3][64];

    for (int i = tid; i < Mn; i += 256)
        keep[i] = (mask[b * Mn + i] == 0.0f) ? 1.0f : 0.0f;
    __syncthreads();

    const float4* p = (const float4*)(ec + ((size_t)b * Mn + mq * 128) * Dn + dbase) + d4;
    const float* kp = keep + mq * 128;

    float4 acc = {0.f, 0.f, 0.f, 0.f};
#pragma unroll 8
    for (int m = 0; m < 128; m++) {
        float4 v = p[(size_t)m * (Dn / 4)];
        const float km = kp[m];
        acc.x = fmaf(v.x, km, acc.x);
        acc.y = fmaf(v.y, km, acc.y);
        acc.z = fmaf(v.z, km, acc.z);
        acc.w = fmaf(v.w, km, acc.w);
    }

    if (mq) part[mq - 1][d4] = acc;
    __syncthreads();
    if (mq == 0) {
        const float4 p0 = part[0][d4];
        const float4 p1 = part[1][d4];
        const float4 p2 = part[2][d4];
        float4 r;
        r.x = (acc.x + p0.x) + (p1.x + p2.x);
        r.y = (acc.y + p0.y) + (p1.y + p2.y);
        r.z = (acc.z + p0.z) + (p1.z + p2.z);
        r.w = (acc.w + p0.w) + (p1.w + p2.w);
        ((float4*)(g_pooled + (size_t)b * Dn + dbase))[d4] = r;
    }
}

// ---------------------------------------------------------------------------
// 2) Layers 1+2: bf16x3 tensor-core GEMM (proven round-11 version).
// ---------------------------------------------------------------------------
template <int LAYER>
__global__ __launch_bounds__(256) void gemm_bf16_kernel(
        const float* __restrict__ W, const float* __restrict__ bias) {
    constexpr int K = (LAYER == 1) ? Dn : U1;
    constexpr int N = (LAYER == 1) ? U1 : U2;
    constexpr bool AHASC = (LAYER != 1);
    const float* Aroot = (LAYER == 1) ? g_pooled : g_h1;
    float* Oroot       = (LAYER == 1) ? g_h1     : g_h2;

    const int c  = blockIdx.z;
    const int b0 = blockIdx.y * 64;
    const int n0 = blockIdx.x * 64;
    const int tid = threadIdx.x;
    const int lane = tid & 31;
    const int warp = tid >> 5;
    const int wm = warp >> 2;       // 0..1
    const int wn = warp & 3;        // 0..3
    const int g  = lane >> 2;       // 0..7
    const int tg = lane & 3;        // 0..3

    __shared__ uint32_t Ah[64][20], Al[64][20];   // [m][k2] packed bf16x2
    __shared__ uint32_t Wh[16][72], Wl[16][72];   // [k2][n] packed bf16x2

    float acc[2][2][4] = {};

    const float* Ag = Aroot + (AHASC ? (size_t)c * Bn * K : 0) + (size_t)b0 * K;
    const float* Wg = W + (size_t)c * K * N + n0;

    const int arow  = tid >> 2;          // 0..63
    const int acol2 = (tid & 3) * 4;     // packed col 0,4,8,12
    const int acolf = (tid & 3) * 8;     // float col
    const int wr2   = tid >> 4;          // 0..15 packed k row
    const int wc4   = (tid & 15) * 4;    // n col 0..60

    float4 gwa = *(const float4*)(Wg + (size_t)(2 * wr2) * N + wc4);
    float4 gwb = *(const float4*)(Wg + (size_t)(2 * wr2 + 1) * N + wc4);

    cudaGridDependencySynchronize();

    for (int k0 = 0; k0 < K; k0 += 32) {
        float4 ga0 = *(const float4*)(Ag + (size_t)arow * K + k0 + acolf);
        float4 ga1 = *(const float4*)(Ag + (size_t)arow * K + k0 + acolf + 4);

        __syncthreads();
        {
            uint32_t hp[4], lp[4];
            split2(ga0.x, ga0.y, hp[0], lp[0]);
            split2(ga0.z, ga0.w, hp[1], lp[1]);
            split2(ga1.x, ga1.y, hp[2], lp[2]);
            split2(ga1.z, ga1.w, hp[3], lp[3]);
            *(uint4*)&Ah[arow][acol2] = make_uint4(hp[0], hp[1], hp[2], hp[3]);
            *(uint4*)&Al[arow][acol2] = make_uint4(lp[0], lp[1], lp[2], lp[3]);
        }
        {
            uint32_t hw[4], lw[4];
            split2(gwa.x, gwb.x, hw[0], lw[0]);
            split2(gwa.y, gwb.y, hw[1], lw[1]);
            split2(gwa.z, gwb.z, hw[2], lw[2]);
            split2(gwa.w, gwb.w, hw[3], lw[3]);
            *(uint4*)&Wh[wr2][wc4] = make_uint4(hw[0], hw[1], hw[2], hw[3]);
            *(uint4*)&Wl[wr2][wc4] = make_uint4(lw[0], lw[1], lw[2], lw[3]);
        }
        __syncthreads();

        if (k0 + 32 < K) {
            gwa = *(const float4*)(Wg + (size_t)(k0 + 32 + 2 * wr2) * N + wc4);
            gwb = *(const float4*)(Wg + (size_t)(k0 + 32 + 2 * wr2 + 1) * N + wc4);
        }

#pragma unroll
        for (int kk = 0; kk < 2; kk++) {
            const int kb2 = kk * 8;
            uint32_t ah[2][4], al_[2][4], bh[2][2], bl[2][2];
#pragma unroll
            for (int mi = 0; mi < 2; mi++) {
                const int m = wm * 32 + mi * 16 + g;
                ah[mi][0]  = Ah[m][kb2 + tg];     ah[mi][1]  = Ah[m + 8][kb2 + tg];
                ah[mi][2]  = Ah[m][kb2 + tg + 4]; ah[mi][3]  = Ah[m + 8][kb2 + tg + 4];
                al_[mi][0] = Al[m][kb2 + tg];     al_[mi][1] = Al[m + 8][kb2 + tg];
                al_[mi][2] = Al[m][kb2 + tg + 4]; al_[mi][3] = Al[m + 8][kb2 + tg + 4];
            }
#pragma unroll
            for (int ni = 0; ni < 2; ni++) {
                const int n = wn * 16 + ni * 8 + g;
                bh[ni][0] = Wh[kb2 + tg][n]; bh[ni][1] = Wh[kb2 + tg + 4][n];
                bl[ni][0] = Wl[kb2 + tg][n]; bl[ni][1] = Wl[kb2 + tg + 4][n];
            }
#pragma unroll
            for (int mi = 0; mi < 2; mi++)
#pragma unroll
                for (int ni = 0; ni < 2; ni++) {
                    mma16(acc[mi][ni], ah[mi],  bh[ni]);
                    mma16(acc[mi][ni], ah[mi],  bl[ni]);
                    mma16(acc[mi][ni], al_[mi], bh[ni]);
                }
        }
    }

#pragma unroll
    for (int mi = 0; mi < 2; mi++) {
#pragma unroll
        for (int ni = 0; ni < 2; ni++) {
            const int ncol = n0 + wn * 16 + ni * 8 + tg * 2;
            const float bx = bias[c * N + ncol];
            const float by = bias[c * N + ncol + 1];
            const int r0 = b0 + wm * 32 + mi * 16 + g;
            float2 o0 = {fmaxf(acc[mi][ni][0] + bx, 0.f),
                         fmaxf(acc[mi][ni][1] + by, 0.f)};
            float2 o1 = {fmaxf(acc[mi][ni][2] + bx, 0.f),
                         fmaxf(acc[mi][ni][3] + by, 0.f)};
            *(float2*)(Oroot + ((size_t)(c * Bn + r0)) * N + ncol)     = o0;
            *(float2*)(Oroot + ((size_t)(c * Bn + r0 + 8)) * N + ncol) = o1;
        }
    }
}

// ---------------------------------------------------------------------------
// 3) Layer 3 + L2 normalize, bf16x3 MMA, bulk-staged (proven round-14).
// ---------------------------------------------------------------------------
#define G3_WH 0
#define G3_WL (128 * 136)
#define G3_AH (2 * 128 * 136)
#define G3_AL (2 * 128 * 136 + 16 * 132)
#define G3_SMEM ((2 * 128 * 136 + 2 * 16 * 132) * 4)

__global__ __launch_bounds__(256) void gemm3_norm_kernel(
        const float* __restrict__ W, const float* __restrict__ bias,
        float* __restrict__ zout) {
    constexpr int K = U2;   // 256
    constexpr int N = U3;   // 128
    const int b0 = blockIdx.x * 16;
    const int c  = blockIdx.y;
    const int tid = threadIdx.x;
    const int lane = tid & 31;
    const int wn = tid >> 5;        // 0..7 (n-warp)
    const int g  = lane >> 2;       // 0..7
    const int tg = lane & 3;        // 0..3

    extern __shared__ uint32_t sm[];
    uint32_t* Wh = sm + G3_WH;      // [128][136]
    uint32_t* Wl = sm + G3_WL;
    uint32_t* Ah = sm + G3_AH;      // [16][132]
    uint32_t* Al = sm + G3_AL;
    __shared__ float rowsq[16][8];

    const float* Ag = g_h2 + ((size_t)c * Bn + b0) * K;
    const float* Wg = W + (size_t)c * K * N;

    // ---- Pre-gate: stage FULL W (external input; overlaps producer) ----
#pragma unroll
    for (int it = 0; it < 8; it++) {
        const int i = tid + it * 256;       // 0..2047
        const int k2r = i >> 4;             // 0..127
        const int nn4 = (i & 15) * 4;       // n col (x4)
        float4 wa = *(const float4*)(Wg + (size_t)(2 * k2r) * N + nn4 * 2);
        float4 wb = *(const float4*)(Wg + (size_t)(2 * k2r + 1) * N + nn4 * 2);
        float4 wc = *(const float4*)(Wg + (size_t)(2 * k2r) * N + nn4 * 2 + 4);
        float4 wd = *(const float4*)(Wg + (size_t)(2 * k2r + 1) * N + nn4 * 2 + 4);
        uint32_t h[8], l[8];
        split2(wa.x, wb.x, h[0], l[0]);
        split2(wa.y, wb.y, h[1], l[1]);
        split2(wa.z, wb.z, h[2], l[2]);
        split2(wa.w, wb.w, h[3], l[3]);
        split2(wc.x, wd.x, h[4], l[4]);
        split2(wc.y, wd.y, h[5], l[5]);
        split2(wc.z, wd.z, h[6], l[6]);
        split2(wc.w, wd.w, h[7], l[7]);
        *(uint4*)&Wh[k2r * 136 + nn4 * 2]     = make_uint4(h[0], h[1], h[2], h[3]);
        *(uint4*)&Wh[k2r * 136 + nn4 * 2 + 4] = make_uint4(h[4], h[5], h[6], h[7]);
        *(uint4*)&Wl[k2r * 136 + nn4 * 2]     = make_uint4(l[0], l[1], l[2], l[3]);
        *(uint4*)&Wl[k2r * 136 + nn4 * 2 + 4] = make_uint4(l[4], l[5], l[6], l[7]);
    }

    cudaGridDependencySynchronize();    // gemm2 must be done before reading h2

    // ---- Post-gate: stage A (16 x 256) ----
#pragma unroll
    for (int it = 0; it < 4; it++) {
        const int i = tid + it * 256;       // 0..1023 float4 index
        const int row = i >> 6;             // 0..15
        const int c4 = (i & 63) * 4;        // float col 0..252
        float4 a = *(const float4*)(Ag + (size_t)row * K + c4);
        uint32_t h0, l0, h1, l1;
        split2(a.x, a.y, h0, l0);
        split2(a.z, a.w, h1, l1);
        *(uint2*)&Ah[row * 132 + (c4 >> 1)] = make_uint2(h0, h1);
        *(uint2*)&Al[row * 132 + (c4 >> 1)] = make_uint2(l0, l1);
    }
    __syncthreads();

    // ---- MMA: 16 k-steps, 2 n-frags per warp ----
    float acc[2][4] = {};
#pragma unroll
    for (int step = 0; step < 16; step++) {
        const int kb2 = step * 8;
        uint32_t ah[4], al_[4], bh[2][2], bl[2][2];
        ah[0]  = Ah[g * 132 + kb2 + tg];     ah[1]  = Ah[(g + 8) * 132 + kb2 + tg];
        ah[2]  = Ah[g * 132 + kb2 + tg + 4]; ah[3]  = Ah[(g + 8) * 132 + kb2 + tg + 4];
        al_[0] = Al[g * 132 + kb2 + tg];     al_[1] = Al[(g + 8) * 132 + kb2 + tg];
        al_[2] = Al[g * 132 + kb2 + tg + 4]; al_[3] = Al[(g + 8) * 132 + kb2 + tg + 4];
#pragma unroll
        for (int ni = 0; ni < 2; ni++) {
            const int n = wn * 16 + ni * 8 + g;
            bh[ni][0] = Wh[(kb2 + tg) * 136 + n]; bh[ni][1] = Wh[(kb2 + tg + 4) * 136 + n];
            bl[ni][0] = Wl[(kb2 + tg) * 136 + n]; bl[ni][1] = Wl[(kb2 + tg + 4) * 136 + n];
        }
#pragma unroll
        for (int ni = 0; ni < 2; ni++) {
            mma16(acc[ni], ah,  bh[ni]);
            mma16(acc[ni], ah,  bl[ni]);
            mma16(acc[ni], al_, bh[ni]);
        }
    }

    // ---- Epilogue: bias + relu, row ssq, normalize, store ----
    float ss[2] = {0.f, 0.f};        // rows g, g+8
#pragma unroll
    for (int ni = 0; ni < 2; ni++) {
        const int ncol = wn * 16 + ni * 8 + tg * 2;
        const float bx = bias[c * N + ncol];
        const float by = bias[c * N + ncol + 1];
        float h0 = fmaxf(acc[ni][0] + bx, 0.f);
        float h1 = fmaxf(acc[ni][1] + by, 0.f);
        float h2 = fmaxf(acc[ni][2] + bx, 0.f);
        float h3 = fmaxf(acc[ni][3] + by, 0.f);
        acc[ni][0] = h0; acc[ni][1] = h1; acc[ni][2] = h2; acc[ni][3] = h3;
        ss[0] = fmaf(h0, h0, ss[0]);
        ss[0] = fmaf(h1, h1, ss[0]);
        ss[1] = fmaf(h2, h2, ss[1]);
        ss[1] = fmaf(h3, h3, ss[1]);
    }
#pragma unroll
    for (int p = 0; p < 2; p++) {
        ss[p] += __shfl_xor_sync(0xffffffffu, ss[p], 1);
        ss[p] += __shfl_xor_sync(0xffffffffu, ss[p], 2);
    }
    if (tg == 0) {
        rowsq[g][wn]     = ss[0];
        rowsq[g + 8][wn] = ss[1];
    }
    __syncthreads();

    float t0 = 0.f, t1 = 0.f;
#pragma unroll
    for (int q = 0; q < 8; q++) { t0 += rowsq[g][q]; t1 += rowsq[g + 8][q]; }
    const float r0 = rsqrtf(fmaxf(t0, 1e-12f));
    const float r1 = rsqrtf(fmaxf(t1, 1e-12f));
#pragma unroll
    for (int ni = 0; ni < 2; ni++) {
        const int ncol = wn * 16 + ni * 8 + tg * 2;
        float2 o0 = {acc[ni][0] * r0, acc[ni][1] * r0};
        float2 o1 = {acc[ni][2] * r1, acc[ni][3] * r1};
        *(float2*)(zout + ((size_t)(c * Bn + b0 + g)) * N + ncol)     = o0;
        *(float2*)(zout + ((size_t)(c * Bn + b0 + g + 8)) * N + ncol) = o1;
    }
}

// ---------------------------------------------------------------------------
// 4) Per-(c,b) contrastive term. grid (C, 16); 8 warps, 2 rows per warp.
// ---------------------------------------------------------------------------
#define ZPAD 132
__global__ __launch_bounds__(256) void loss_kernel(const float* __restrict__ z,
                                                   const int* __restrict__ label) {
    extern __shared__ float zs[];          // [256][ZPAD]
    __shared__ int slab[Bn];
    __shared__ int wsum[8];

    const int c = blockIdx.x;
    const int tid = threadIdx.x;
    const int lane = tid & 31;
    const int warp = tid >> 5;

    const int myl = label[tid * Cn + c];
    slab[tid] = myl;
    int s = myl;
#pragma unroll
    for (int o = 16; o; o >>= 1) s += __shfl_xor_sync(0xffffffffu, s, o);
    if (lane == 0) wsum[warp] = s;

    cudaGridDependencySynchronize();

    const float* zc = z + (size_t)c * Bn * U3;
    for (int idx = tid; idx < Bn * U3 / 4; idx += 256) {
        const int row = idx >> 5;
        const int c4 = idx & 31;
        float4 v = *(const float4*)(zc + (size_t)row * U3 + c4 * 4);
        *(float4*)&zs[row * ZPAD + c4 * 4] = v;
    }
    __syncthreads();
    int nump = 0;
#pragma unroll
    for (int i = 0; i < 8; i++) nump += wsum[i];

    const int bb = blockIdx.y * 16 + warp * 2;

    int lb[2];
    const float* zb[2];
#pragma unroll
    for (int i = 0; i < 2; i++) {
        lb[i] = slab[bb + i];
        zb[i] = &zs[(bb + i) * ZPAD];
    }

    float es[2] = {0.f, 0.f};
    float ps[2] = {0.f, 0.f};

#pragma unroll
    for (int kk = 0; kk < 8; kk++) {
        const int k = kk * 32 + lane;
        const float* zk = &zs[k * ZPAD];
        float s0 = 0.f, s1 = 0.f;
#pragma unroll
        for (int j = 0; j < U3; j += 4) {
            float4 x  = *(const float4*)(zk + j);
            float4 a0 = *(const float4*)(zb[0] + j);
            float4 a1 = *(const float4*)(zb[1] + j);
            s0 = fmaf(a0.x, x.x, s0); s0 = fmaf(a0.y, x.y, s0);
            s0 = fmaf(a0.z, x.z, s0); s0 = fmaf(a0.w, x.w, s0);
            s1 = fmaf(a1.x, x.x, s1); s1 = fmaf(a1.y, x.y, s1);
            s1 = fmaf(a1.z, x.z, s1); s1 = fmaf(a1.w, x.w, s1);
        }
        const int sk = slab[k];
        float sv[2] = {s0, s1};
#pragma unroll
        for (int i = 0; i < 2; i++) {
            const float ipv = (k == bb + i) ? 0.0f : sv[i] * 2.0f;  // /TEMP
            es[i] += __expf(ipv);
            if (sk == lb[i]) ps[i] += ipv;
        }
    }

#pragma unroll
    for (int i = 0; i < 2; i++) {
#pragma unroll
        for (int o = 16; o; o >>= 1) {
            es[i] += __shfl_xor_sync(0xffffffffu, es[i], o);
            ps[i] += __shfl_xor_sync(0xffffffffu, ps[i], o);
        }
    }
    if (lane == 0) {
#pragma unroll
        for (int i = 0; i < 2; i++) {
            const int numv = lb[i] ? nump : (Bn - nump);
            g_term[c * Bn + bb + i] = ps[i] / (float)numv - logf(es[i]);
        }
    }
}

// ---------------------------------------------------------------------------
// 5) Reduce terms -> losses[c]
// ---------------------------------------------------------------------------
__global__ __launch_bounds__(256) void final_kernel(float* __restrict__ out) {
    __shared__ float red[Bn];
    const int c = blockIdx.x;
    const int tid = threadIdx.x;
    cudaGridDependencySynchronize();
    red[tid] = g_term[c * Bn + tid];
    __syncthreads();
    for (int s = 128; s; s >>= 1) {
        if (tid < s) red[tid] += red[tid + s];
        __syncthreads();
    }
    if (tid == 0) out[(size_t)Cn * Bn * U3 + c] = -red[0];
}

// ---------------------------------------------------------------------------
// Launch with PDL on the capture stream.
// ---------------------------------------------------------------------------
template <typename F, typename... Args>
static void launch_pdl(F f, dim3 grid, dim3 block, size_t smem, Args... args) {
    cudaLaunchConfig_t cfg = {};
    cfg.gridDim = grid;
    cfg.blockDim = block;
    cfg.dynamicSmemBytes = smem;
    cfg.stream = 0;
    cudaLaunchAttribute at[1];
    at[0].id = cudaLaunchAttributeProgrammaticStreamSerialization;
    at[0].val.programmaticStreamSerializationAllowed = 1;
    cfg.attrs = at;
    cfg.numAttrs = 1;
    cudaLaunchKernelEx(&cfg, f, args...);
}

extern "C" void kernel_launch(void* const* d_in, const int* in_sizes, int n_in,
                              void* d_out, int out_size) {
    const float* ec    = (const float*)d_in[0];
    const float* mask  = (const float*)d_in[1];
    const int*   label = (const int*)d_in[2];
    const float* W1    = (const float*)d_in[3];
    const float* b1    = (const float*)d_in[4];
    const float* W2    = (const float*)d_in[5];
    const float* b2    = (const float*)d_in[6];
    const float* W3    = (const float*)d_in[7];
    const float* b3    = (const float*)d_in[8];
    float* out = (float*)d_out;

    const int loss_smem = Bn * ZPAD * (int)sizeof(float);
    static int inited = 0;
    if (!inited) {
        cudaFuncSetAttribute(loss_kernel,
                             cudaFuncAttributeMaxDynamicSharedMemorySize, loss_smem);
        cudaFuncSetAttribute(gemm3_norm_kernel,
                             cudaFuncAttributeMaxDynamicSharedMemorySize, G3_SMEM);
        inited = 1;
    }

    pool_kernel<<<dim3(Bn, 2), 256>>>(ec, mask);
    launch_pdl(gemm_bf16_kernel<1>, dim3(U1 / 64, Bn / 64, Cn), dim3(256), 0, W1, b1);
    launch_pdl(gemm_bf16_kernel<2>, dim3(U2 / 64, Bn / 64, Cn), dim3(256), 0, W2, b2);
    launch_pdl(gemm3_norm_kernel, dim3(Bn / 16, Cn), dim3(256), (size_t)G3_SMEM, W3, b3, out);
    launch_pdl(loss_kernel, dim3(Cn, Bn / 16), dim3(256), (size_t)loss_smem, out, label);
    launch_pdl(final_kernel, dim3(Cn), dim3(256), 0, out);
}

// round 16
// speedup vs baseline: 1.2464x; 1.1812x over previous
#include <cuda_runtime.h>
#include <math.h>
#include <stdint.h>

#define Bn 256
#define Mn 512
#define Dn 512
#define Cn 8
#define U1 512
#define U2 256
#define U3 128

// Scratch (device-code-only references)
__device__ float g_pooled[Bn * Dn];          // (B, D)
__device__ float g_h1[Cn * Bn * U1];         // (C, B, 512)
__device__ float g_h2[Cn * Bn * U2];         // (C, B, 256)
__device__ float g_term[Cn * Bn];            // per (c,b) loss term

// ---------------------------------------------------------------------------
// bf16 helpers
// ---------------------------------------------------------------------------
__device__ __forceinline__ uint32_t packbf(float lo, float hi) {
    uint32_t r;
    asm("cvt.rn.bf16x2.f32 %0, %1, %2;" : "=r"(r) : "f"(hi), "f"(lo));
    return r;
}
__device__ __forceinline__ void split2(float x0, float x1,
                                       uint32_t& h, uint32_t& l) {
    h = packbf(x0, x1);
    const float h0 = __uint_as_float(h << 16);
    const float h1 = __uint_as_float(h & 0xffff0000u);
    l = packbf(x0 - h0, x1 - h1);
}
__device__ __forceinline__ void mma16(float* d, const uint32_t* a, const uint32_t* b) {
    asm("mma.sync.aligned.m16n8k16.row.col.f32.bf16.bf16.f32 "
        "{%0,%1,%2,%3}, {%4,%5,%6,%7}, {%8,%9}, {%0,%1,%2,%3};"
        : "+f"(d[0]), "+f"(d[1]), "+f"(d[2]), "+f"(d[3])
        : "r"(a[0]), "r"(a[1]), "r"(a[2]), "r"(a[3]), "r"(b[0]), "r"(b[1]));
}

// ---------------------------------------------------------------------------
// 1) Masked sum pooling with row compaction: only kept rows (mask==0) are
//    loaded from DRAM (~halves pool traffic; numerically identical since
//    skipped terms are exact zeros). grid (Bn, 2), 256 threads.
//    d4 = tid&63 (float4 over 256-float d-slice), mq = tid>>6 interleaves
//    over the compacted list (i % 4 == mq). Fixed-order smem combine.
// ---------------------------------------------------------------------------
__global__ __launch_bounds__(256) void pool_kernel(const float* __restrict__ ec,
                                                   const float* __restrict__ mask) {
    const int b = blockIdx.x;
    const int dbase = blockIdx.y * 256;
    const int tid = threadIdx.x;
    const int lane = tid & 31;
    const int warp = tid >> 5;
    const int d4 = tid & 63;        // 0..63 (float4 within 256-float slice)
    const int mq = tid >> 6;        // 0..3 (interleave class)

    __shared__ short list[Mn];
    __shared__ int cnt[16];
    __shared__ int off[17];
    __shared__ float4 part[3][64];

    // ---- order-preserving compaction of kept rows (16 chunks of 32) ----
#pragma unroll
    for (int it = 0; it < 2; it++) {
        const int chunk = warp + it * 8;
        const int row = chunk * 32 + lane;
        const bool keep = (mask[b * Mn + row] == 0.0f);
        const unsigned bal = __ballot_sync(0xffffffffu, keep);
        if (lane == 0) cnt[chunk] = __popc(bal);
    }
    __syncthreads();
    if (tid == 0) {
        int s = 0;
#pragma unroll
        for (int j = 0; j < 16; j++) { off[j] = s; s += cnt[j]; }
        off[16] = s;
    }
    __syncthreads();
#pragma unroll
    for (int it = 0; it < 2; it++) {
        const int chunk = warp + it * 8;
        const int row = chunk * 32 + lane;
        const bool keep = (mask[b * Mn + row] == 0.0f);
        const unsigned bal = __ballot_sync(0xffffffffu, keep);
        const int rank = __popc(bal & ((1u << lane) - 1u));
        if (keep) list[off[chunk] + rank] = (short)row;
    }
    __syncthreads();
    const int nkeep = off[16];

    // ---- dense accumulation over kept rows only ----
    const float* base = ec + (size_t)b * Mn * Dn + dbase + d4 * 4;
    float4 acc = {0.f, 0.f, 0.f, 0.f};
#pragma unroll 4
    for (int i = mq; i < nkeep; i += 4) {
        const int row = list[i];
        float4 v = *(const float4*)(base + (size_t)row * Dn);
        acc.x += v.x; acc.y += v.y; acc.z += v.z; acc.w += v.w;
    }

    if (mq) part[mq - 1][d4] = acc;
    __syncthreads();
    if (mq == 0) {
        const float4 p0 = part[0][d4];
        const float4 p1 = part[1][d4];
        const float4 p2 = part[2][d4];
        float4 r;
        r.x = (acc.x + p0.x) + (p1.x + p2.x);
        r.y = (acc.y + p0.y) + (p1.y + p2.y);
        r.z = (acc.z + p0.z) + (p1.z + p2.z);
        r.w = (acc.w + p0.w) + (p1.w + p2.w);
        ((float4*)(g_pooled + (size_t)b * Dn + dbase))[d4] = r;
    }
}

// ---------------------------------------------------------------------------
// 2) Layers 1+2: bf16x3 tensor-core GEMM (proven round-11 version).
// ---------------------------------------------------------------------------
template <int LAYER>
__global__ __launch_bounds__(256) void gemm_bf16_kernel(
        const float* __restrict__ W, const float* __restrict__ bias) {
    constexpr int K = (LAYER == 1) ? Dn : U1;
    constexpr int N = (LAYER == 1) ? U1 : U2;
    constexpr bool AHASC = (LAYER != 1);
    const float* Aroot = (LAYER == 1) ? g_pooled : g_h1;
    float* Oroot       = (LAYER == 1) ? g_h1     : g_h2;

    const int c  = blockIdx.z;
    const int b0 = blockIdx.y * 64;
    const int n0 = blockIdx.x * 64;
    const int tid = threadIdx.x;
    const int lane = tid & 31;
    const int warp = tid >> 5;
    const int wm = warp >> 2;       // 0..1
    const int wn = warp & 3;        // 0..3
    const int g  = lane >> 2;       // 0..7
    const int tg = lane & 3;        // 0..3

    __shared__ uint32_t Ah[64][20], Al[64][20];   // [m][k2] packed bf16x2
    __shared__ uint32_t Wh[16][72], Wl[16][72];   // [k2][n] packed bf16x2

    float acc[2][2][4] = {};

    const float* Ag = Aroot + (AHASC ? (size_t)c * Bn * K : 0) + (size_t)b0 * K;
    const float* Wg = W + (size_t)c * K * N + n0;

    const int arow  = tid >> 2;          // 0..63
    const int acol2 = (tid & 3) * 4;     // packed col 0,4,8,12
    const int acolf = (tid & 3) * 8;     // float col
    const int wr2   = tid >> 4;          // 0..15 packed k row
    const int wc4   = (tid & 15) * 4;    // n col 0..60

    float4 gwa = *(const float4*)(Wg + (size_t)(2 * wr2) * N + wc4);
    float4 gwb = *(const float4*)(Wg + (size_t)(2 * wr2 + 1) * N + wc4);

    cudaGridDependencySynchronize();

    for (int k0 = 0; k0 < K; k0 += 32) {
        float4 ga0 = *(const float4*)(Ag + (size_t)arow * K + k0 + acolf);
        float4 ga1 = *(const float4*)(Ag + (size_t)arow * K + k0 + acolf + 4);

        __syncthreads();
        {
            uint32_t hp[4], lp[4];
            split2(ga0.x, ga0.y, hp[0], lp[0]);
            split2(ga0.z, ga0.w, hp[1], lp[1]);
            split2(ga1.x, ga1.y, hp[2], lp[2]);
            split2(ga1.z, ga1.w, hp[3], lp[3]);
            *(uint4*)&Ah[arow][acol2] = make_uint4(hp[0], hp[1], hp[2], hp[3]);
            *(uint4*)&Al[arow][acol2] = make_uint4(lp[0], lp[1], lp[2], lp[3]);
        }
        {
            uint32_t hw[4], lw[4];
            split2(gwa.x, gwb.x, hw[0], lw[0]);
            split2(gwa.y, gwb.y, hw[1], lw[1]);
            split2(gwa.z, gwb.z, hw[2], lw[2]);
            split2(gwa.w, gwb.w, hw[3], lw[3]);
            *(uint4*)&Wh[wr2][wc4] = make_uint4(hw[0], hw[1], hw[2], hw[3]);
            *(uint4*)&Wl[wr2][wc4] = make_uint4(lw[0], lw[1], lw[2], lw[3]);
        }
        __syncthreads();

        if (k0 + 32 < K) {
            gwa = *(const float4*)(Wg + (size_t)(k0 + 32 + 2 * wr2) * N + wc4);
            gwb = *(const float4*)(Wg + (size_t)(k0 + 32 + 2 * wr2 + 1) * N + wc4);
        }

#pragma unroll
        for (int kk = 0; kk < 2; kk++) {
            const int kb2 = kk * 8;
            uint32_t ah[2][4], al_[2][4], bh[2][2], bl[2][2];
#pragma unroll
            for (int mi = 0; mi < 2; mi++) {
                const int m = wm * 32 + mi * 16 + g;
                ah[mi][0]  = Ah[m][kb2 + tg];     ah[mi][1]  = Ah[m + 8][kb2 + tg];
                ah[mi][2]  = Ah[m][kb2 + tg + 4]; ah[mi][3]  = Ah[m + 8][kb2 + tg + 4];
                al_[mi][0] = Al[m][kb2 + tg];     al_[mi][1] = Al[m + 8][kb2 + tg];
                al_[mi][2] = Al[m][kb2 + tg + 4]; al_[mi][3] = Al[m + 8][kb2 + tg + 4];
            }
#pragma unroll
            for (int ni = 0; ni < 2; ni++) {
                const int n = wn * 16 + ni * 8 + g;
                bh[ni][0] = Wh[kb2 + tg][n]; bh[ni][1] = Wh[kb2 + tg + 4][n];
                bl[ni][0] = Wl[kb2 + tg][n]; bl[ni][1] = Wl[kb2 + tg + 4][n];
            }
#pragma unroll
            for (int mi = 0; mi < 2; mi++)
#pragma unroll
                for (int ni = 0; ni < 2; ni++) {
                    mma16(acc[mi][ni], ah[mi],  bh[ni]);
                    mma16(acc[mi][ni], ah[mi],  bl[ni]);
                    mma16(acc[mi][ni], al_[mi], bh[ni]);
                }
        }
    }

#pragma unroll
    for (int mi = 0; mi < 2; mi++) {
#pragma unroll
        for (int ni = 0; ni < 2; ni++) {
            const int ncol = n0 + wn * 16 + ni * 8 + tg * 2;
            const float bx = bias[c * N + ncol];
            const float by = bias[c * N + ncol + 1];
            const int r0 = b0 + wm * 32 + mi * 16 + g;
            float2 o0 = {fmaxf(acc[mi][ni][0] + bx, 0.f),
                         fmaxf(acc[mi][ni][1] + by, 0.f)};
            float2 o1 = {fmaxf(acc[mi][ni][2] + bx, 0.f),
                         fmaxf(acc[mi][ni][3] + by, 0.f)};
            *(float2*)(Oroot + ((size_t)(c * Bn + r0)) * N + ncol)     = o0;
            *(float2*)(Oroot + ((size_t)(c * Bn + r0 + 8)) * N + ncol) = o1;
        }
    }
}

// ---------------------------------------------------------------------------
// 3) Layer 3 + L2 normalize, bf16x3 MMA, bulk-staged (proven round-14).
// ---------------------------------------------------------------------------
#define G3_WH 0
#define G3_WL (128 * 136)
#define G3_AH (2 * 128 * 136)
#define G3_AL (2 * 128 * 136 + 16 * 132)
#define G3_SMEM ((2 * 128 * 136 + 2 * 16 * 132) * 4)

__global__ __launch_bounds__(256) void gemm3_norm_kernel(
        const float* __restrict__ W, const float* __restrict__ bias,
        float* __restrict__ zout) {
    constexpr int K = U2;   // 256
    constexpr int N = U3;   // 128
    const int b0 = blockIdx.x * 16;
    const int c  = blockIdx.y;
    const int tid = threadIdx.x;
    const int lane = tid & 31;
    const int wn = tid >> 5;        // 0..7 (n-warp)
    const int g  = lane >> 2;       // 0..7
    const int tg = lane & 3;        // 0..3

    extern __shared__ uint32_t sm[];
    uint32_t* Wh = sm + G3_WH;      // [128][136]
    uint32_t* Wl = sm + G3_WL;
    uint32_t* Ah = sm + G3_AH;      // [16][132]
    uint32_t* Al = sm + G3_AL;
    __shared__ float rowsq[16][8];

    const float* Ag = g_h2 + ((size_t)c * Bn + b0) * K;
    const float* Wg = W + (size_t)c * K * N;

    // ---- Pre-gate: stage FULL W (external input; overlaps producer) ----
#pragma unroll
    for (int it = 0; it < 8; it++) {
        const int i = tid + it * 256;       // 0..2047
        const int k2r = i >> 4;             // 0..127
        const int nn4 = (i & 15) * 4;       // n col (x4)
        float4 wa = *(const float4*)(Wg + (size_t)(2 * k2r) * N + nn4 * 2);
        float4 wb = *(const float4*)(Wg + (size_t)(2 * k2r + 1) * N + nn4 * 2);
        float4 wc = *(const float4*)(Wg + (size_t)(2 * k2r) * N + nn4 * 2 + 4);
        float4 wd = *(const float4*)(Wg + (size_t)(2 * k2r + 1) * N + nn4 * 2 + 4);
        uint32_t h[8], l[8];
        split2(wa.x, wb.x, h[0], l[0]);
        split2(wa.y, wb.y, h[1], l[1]);
        split2(wa.z, wb.z, h[2], l[2]);
        split2(wa.w, wb.w, h[3], l[3]);
        split2(wc.x, wd.x, h[4], l[4]);
        split2(wc.y, wd.y, h[5], l[5]);
        split2(wc.z, wd.z, h[6], l[6]);
        split2(wc.w, wd.w, h[7], l[7]);
        *(uint4*)&Wh[k2r * 136 + nn4 * 2]     = make_uint4(h[0], h[1], h[2], h[3]);
        *(uint4*)&Wh[k2r * 136 + nn4 * 2 + 4] = make_uint4(h[4], h[5], h[6], h[7]);
        *(uint4*)&Wl[k2r * 136 + nn4 * 2]     = make_uint4(l[0], l[1], l[2], l[3]);
        *(uint4*)&Wl[k2r * 136 + nn4 * 2 + 4] = make_uint4(l[4], l[5], l[6], l[7]);
    }

    cudaGridDependencySynchronize();    // gemm2 must be done before reading h2

    // ---- Post-gate: stage A (16 x 256) ----
#pragma unroll
    for (int it = 0; it < 4; it++) {
        const int i = tid + it * 256;       // 0..1023 float4 index
        const int row = i >> 6;             // 0..15
        const int c4 = (i & 63) * 4;        // float col 0..252
        float4 a = *(const float4*)(Ag + (size_t)row * K + c4);
        uint32_t h0, l0, h1, l1;
        split2(a.x, a.y, h0, l0);
        split2(a.z, a.w, h1, l1);
        *(uint2*)&Ah[row * 132 + (c4 >> 1)] = make_uint2(h0, h1);
        *(uint2*)&Al[row * 132 + (c4 >> 1)] = make_uint2(l0, l1);
    }
    __syncthreads();

    // ---- MMA: 16 k-steps, 2 n-frags per warp ----
    float acc[2][4] = {};
#pragma unroll
    for (int step = 0; step < 16; step++) {
        const int kb2 = step * 8;
        uint32_t ah[4], al_[4], bh[2][2], bl[2][2];
        ah[0]  = Ah[g * 132 + kb2 + tg];     ah[1]  = Ah[(g + 8) * 132 + kb2 + tg];
        ah[2]  = Ah[g * 132 + kb2 + tg + 4]; ah[3]  = Ah[(g + 8) * 132 + kb2 + tg + 4];
        al_[0] = Al[g * 132 + kb2 + tg];     al_[1] = Al[(g + 8) * 132 + kb2 + tg];
        al_[2] = Al[g * 132 + kb2 + tg + 4]; al_[3] = Al[(g + 8) * 132 + kb2 + tg + 4];
#pragma unroll
        for (int ni = 0; ni < 2; ni++) {
            const int n = wn * 16 + ni * 8 + g;
            bh[ni][0] = Wh[(kb2 + tg) * 136 + n]; bh[ni][1] = Wh[(kb2 + tg + 4) * 136 + n];
            bl[ni][0] = Wl[(kb2 + tg) * 136 + n]; bl[ni][1] = Wl[(kb2 + tg + 4) * 136 + n];
        }
#pragma unroll
        for (int ni = 0; ni < 2; ni++) {
            mma16(acc[ni], ah,  bh[ni]);
            mma16(acc[ni], ah,  bl[ni]);
            mma16(acc[ni], al_, bh[ni]);
        }
    }

    // ---- Epilogue: bias + relu, row ssq, normalize, store ----
    float ss[2] = {0.f, 0.f};        // rows g, g+8
#pragma unroll
    for (int ni = 0; ni < 2; ni++) {
        const int ncol = wn * 16 + ni * 8 + tg * 2;
        const float bx = bias[c * N + ncol];
        const float by = bias[c * N + ncol + 1];
        float h0 = fmaxf(acc[ni][0] + bx, 0.f);
        float h1 = fmaxf(acc[ni][1] + by, 0.f);
        float h2 = fmaxf(acc[ni][2] + bx, 0.f);
        float h3 = fmaxf(acc[ni][3] + by, 0.f);
        acc[ni][0] = h0; acc[ni][1] = h1; acc[ni][2] = h2; acc[ni][3] = h3;
        ss[0] = fmaf(h0, h0, ss[0]);
        ss[0] = fmaf(h1, h1, ss[0]);
        ss[1] = fmaf(h2, h2, ss[1]);
        ss[1] = fmaf(h3, h3, ss[1]);
    }
#pragma unroll
    for (int p = 0; p < 2; p++) {
        ss[p] += __shfl_xor_sync(0xffffffffu, ss[p], 1);
        ss[p] += __shfl_xor_sync(0xffffffffu, ss[p], 2);
    }
    if (tg == 0) {
        rowsq[g][wn]     = ss[0];
        rowsq[g + 8][wn] = ss[1];
    }
    __syncthreads();

    float t0 = 0.f, t1 = 0.f;
#pragma unroll
    for (int q = 0; q < 8; q++) { t0 += rowsq[g][q]; t1 += rowsq[g + 8][q]; }
    const float r0 = rsqrtf(fmaxf(t0, 1e-12f));
    const float r1 = rsqrtf(fmaxf(t1, 1e-12f));
#pragma unroll
    for (int ni = 0; ni < 2; ni++) {
        const int ncol = wn * 16 + ni * 8 + tg * 2;
        float2 o0 = {acc[ni][0] * r0, acc[ni][1] * r0};
        float2 o1 = {acc[ni][2] * r1, acc[ni][3] * r1};
        *(float2*)(zout + ((size_t)(c * Bn + b0 + g)) * N + ncol)     = o0;
        *(float2*)(zout + ((size_t)(c * Bn + b0 + g + 8)) * N + ncol) = o1;
    }
}

// ---------------------------------------------------------------------------
// 4) Per-(c,b) contrastive term. grid (C, 16); 8 warps, 2 rows per warp.
// ---------------------------------------------------------------------------
#define ZPAD 132
__global__ __launch_bounds__(256) void loss_kernel(const float* __restrict__ z,
                                                   const int* __restrict__ label) {
    extern __shared__ float zs[];          // [256][ZPAD]
    __shared__ int slab[Bn];
    __shared__ int wsum[8];

    const int c = blockIdx.x;
    const int tid = threadIdx.x;
    const int lane = tid & 31;
    const int warp = tid >> 5;

    const int myl = label[tid * Cn + c];
    slab[tid] = myl;
    int s = myl;
#pragma unroll
    for (int o = 16; o; o >>= 1) s += __shfl_xor_sync(0xffffffffu, s, o);
    if (lane == 0) wsum[warp] = s;

    cudaGridDependencySynchronize();

    const float* zc = z + (size_t)c * Bn * U3;
    for (int idx = tid; idx < Bn * U3 / 4; idx += 256) {
        const int row = idx >> 5;
        const int c4 = idx & 31;
        float4 v = *(const float4*)(zc + (size_t)row * U3 + c4 * 4);
        *(float4*)&zs[row * ZPAD + c4 * 4] = v;
    }
    __syncthreads();
    int nump = 0;
#pragma unroll
    for (int i = 0; i < 8; i++) nump += wsum[i];

    const int bb = blockIdx.y * 16 + warp * 2;

    int lb[2];
    const float* zb[2];
#pragma unroll
    for (int i = 0; i < 2; i++) {
        lb[i] = slab[bb + i];
        zb[i] = &zs[(bb + i) * ZPAD];
    }

    float es[2] = {0.f, 0.f};
    float ps[2] = {0.f, 0.f};

#pragma unroll
    for (int kk = 0; kk < 8; kk++) {
        const int k = kk * 32 + lane;
        const float* zk = &zs[k * ZPAD];
        float s0 = 0.f, s1 = 0.f;
#pragma unroll
        for (int j = 0; j < U3; j += 4) {
            float4 x  = *(const float4*)(zk + j);
            float4 a0 = *(const float4*)(zb[0] + j);
            float4 a1 = *(const float4*)(zb[1] + j);
            s0 = fmaf(a0.x, x.x, s0); s0 = fmaf(a0.y, x.y, s0);
            s0 = fmaf(a0.z, x.z, s0); s0 = fmaf(a0.w, x.w, s0);
            s1 = fmaf(a1.x, x.x, s1); s1 = fmaf(a1.y, x.y, s1);
            s1 = fmaf(a1.z, x.z, s1); s1 = fmaf(a1.w, x.w, s1);
        }
        const int sk = slab[k];
        float sv[2] = {s0, s1};
#pragma unroll
        for (int i = 0; i < 2; i++) {
            const float ipv = (k == bb + i) ? 0.0f : sv[i] * 2.0f;  // /TEMP
            es[i] += __expf(ipv);
            if (sk == lb[i]) ps[i] += ipv;
        }
    }

#pragma unroll
    for (int i = 0; i < 2; i++) {
#pragma unroll
        for (int o = 16; o; o >>= 1) {
            es[i] += __shfl_xor_sync(0xffffffffu, es[i], o);
            ps[i] += __shfl_xor_sync(0xffffffffu, ps[i], o);
        }
    }
    if (lane == 0) {
#pragma unroll
        for (int i = 0; i < 2; i++) {
            const int numv = lb[i] ? nump : (Bn - nump);
            g_term[c * Bn + bb + i] = ps[i] / (float)numv - logf(es[i]);
        }
    }
}

// ---------------------------------------------------------------------------
// 5) Reduce terms -> losses[c]
// ---------------------------------------------------------------------------
__global__ __launch_bounds__(256) void final_kernel(float* __restrict__ out) {
    __shared__ float red[Bn];
    const int c = blockIdx.x;
    const int tid = threadIdx.x;
    cudaGridDependencySynchronize();
    red[tid] = g_term[c * Bn + tid];
    __syncthreads();
    for (int s = 128; s; s >>= 1) {
        if (tid < s) red[tid] += red[tid + s];
        __syncthreads();
    }
    if (tid == 0) out[(size_t)Cn * Bn * U3 + c] = -red[0];
}

// ---------------------------------------------------------------------------
// Launch with PDL on the capture stream.
// ---------------------------------------------------------------------------
template <typename F, typename... Args>
static void launch_pdl(F f, dim3 grid, dim3 block, size_t smem, Args... args) {
    cudaLaunchConfig_t cfg = {};
    cfg.gridDim = grid;
    cfg.blockDim = block;
    cfg.dynamicSmemBytes = smem;
    cfg.stream = 0;
    cudaLaunchAttribute at[1];
    at[0].id = cudaLaunchAttributeProgrammaticStreamSerialization;
    at[0].val.programmaticStreamSerializationAllowed = 1;
    cfg.attrs = at;
    cfg.numAttrs = 1;
    cudaLaunchKernelEx(&cfg, f, args...);
}

extern "C" void kernel_launch(void* const* d_in, const int* in_sizes, int n_in,
                              void* d_out, int out_size) {
    const float* ec    = (const float*)d_in[0];
    const float* mask  = (const float*)d_in[1];
    const int*   label = (const int*)d_in[2];
    const float* W1    = (const float*)d_in[3];
    const float* b1    = (const float*)d_in[4];
    const float* W2    = (const float*)d_in[5];
    const float* b2    = (const float*)d_in[6];
    const float* W3    = (const float*)d_in[7];
    const float* b3    = (const float*)d_in[8];
    float* out = (float*)d_out;

    const int loss_smem = Bn * ZPAD * (int)sizeof(float);
    static int inited = 0;
    if (!inited) {
        cudaFuncSetAttribute(loss_kernel,
                             cudaFuncAttributeMaxDynamicSharedMemorySize, loss_smem);
        cudaFuncSetAttribute(gemm3_norm_kernel,
                             cudaFuncAttributeMaxDynamicSharedMemorySize, G3_SMEM);
        inited = 1;
    }

    pool_kernel<<<dim3(Bn, 2), 256>>>(ec, mask);
    launch_pdl(gemm_bf16_kernel<1>, dim3(U1 / 64, Bn / 64, Cn), dim3(256), 0, W1, b1);
    launch_pdl(gemm_bf16_kernel<2>, dim3(U2 / 64, Bn / 64, Cn), dim3(256), 0, W2, b2);
    launch_pdl(gemm3_norm_kernel, dim3(Bn / 16, Cn), dim3(256), (size_t)G3_SMEM, W3, b3, out);
    launch_pdl(loss_kernel, dim3(Cn, Bn / 16), dim3(256), (size_t)loss_smem, out, label);
    launch_pdl(final_kernel, dim3(Cn), dim3(256), 0, out);
}